// round 3
// baseline (speedup 1.0000x reference)
#include <cuda_runtime.h>
#include <math.h>

#define SEQ    2048
#define BATCH  2
#define DMODEL 1024
#define NH     16
#define HD     64
#define DFF    4096
#define ROWS   (SEQ*BATCH)   // 4096

// ---------------- scratch (device globals; no allocation allowed) ----------
__device__ float g_h   [ROWS*DMODEL];     // LN1 out
__device__ float g_qkv [ROWS*3*DMODEL];   // qkv
__device__ float g_attn[ROWS*DMODEL];     // attention out (pre-proj)
__device__ float g_x1  [ROWS*DMODEL];     // x + attn_proj
__device__ float g_h2  [ROWS*DMODEL];     // LN2 out
__device__ float g_m   [ROWS*DFF];        // gelu(fc) out

// ---------------- LayerNorm: one CTA per row, 256 threads, float4 ----------
__global__ void ln_kernel(const float* __restrict__ x,
                          const float* __restrict__ g,
                          const float* __restrict__ b,
                          float* __restrict__ y)
{
    int row = blockIdx.x;
    int tid = threadIdx.x;
    const float4* xr = reinterpret_cast<const float4*>(x + (size_t)row * DMODEL);
    float4 v = xr[tid];

    __shared__ float red[8];
    __shared__ float stat[2];

    float s = v.x + v.y + v.z + v.w;
    #pragma unroll
    for (int o = 16; o; o >>= 1) s += __shfl_xor_sync(0xffffffffu, s, o);
    if ((tid & 31) == 0) red[tid >> 5] = s;
    __syncthreads();
    if (tid == 0) {
        float t = 0.f;
        #pragma unroll
        for (int i = 0; i < 8; i++) t += red[i];
        stat[0] = t * (1.0f / DMODEL);
    }
    __syncthreads();
    float mu = stat[0];

    float dx = v.x - mu, dy = v.y - mu, dz = v.z - mu, dw = v.w - mu;
    float s2 = dx*dx + dy*dy + dz*dz + dw*dw;
    #pragma unroll
    for (int o = 16; o; o >>= 1) s2 += __shfl_xor_sync(0xffffffffu, s2, o);
    if ((tid & 31) == 0) red[tid >> 5] = s2;
    __syncthreads();
    if (tid == 0) {
        float t = 0.f;
        #pragma unroll
        for (int i = 0; i < 8; i++) t += red[i];
        stat[1] = rsqrtf(t * (1.0f / DMODEL) + 1e-5f);
    }
    __syncthreads();
    float rstd = stat[1];

    const float4* gr = reinterpret_cast<const float4*>(g);
    const float4* br = reinterpret_cast<const float4*>(b);
    float4 gv = gr[tid], bv = br[tid];
    float4 o;
    o.x = dx * rstd * gv.x + bv.x;
    o.y = dy * rstd * gv.y + bv.y;
    o.z = dz * rstd * gv.z + bv.z;
    o.w = dw * rstd * gv.w + bv.w;
    reinterpret_cast<float4*>(y + (size_t)row * DMODEL)[tid] = o;
}

// ---------------- GELU (tanh approximation, JAX default) -------------------
__device__ __forceinline__ float gelu_f(float v)
{
    float c = v + 0.044715f * v * v * v;
    return 0.5f * v * (1.0f + tanhf(0.7978845608028654f * c));
}

// ---------------- Tiled SGEMM: C[M,N] = A[M,K] @ B[K,N] + epilogue ---------
// BM=BN=128, BK=16, 256 threads, 8x8 micro-tile.
// EPI: 0 = +bias, 1 = +bias+res, 2 = gelu(+bias)
template<int EPI>
__global__ void __launch_bounds__(256)
sgemm_kernel(const float* __restrict__ A, const float* __restrict__ B,
             const float* __restrict__ bias, const float* __restrict__ res,
             float* __restrict__ C, int M, int N, int K)
{
    __shared__ float As[16][132];   // stored transposed: As[k][m]
    __shared__ float Bs[16][128];

    int tid = threadIdx.x;
    int tx = tid & 15, ty = tid >> 4;
    int row0 = blockIdx.y * 128, col0 = blockIdx.x * 128;

    float acc[8][8] = {};

    int arow = tid >> 2;            // 0..63
    int acol = (tid & 3) * 4;       // 0,4,8,12
    int brow = tid >> 5;            // 0..7
    int bcol = (tid & 31) * 4;      // 0..124

    const float* Aptr = A + (size_t)(row0 + arow) * K + acol;
    const float* Bptr = B + (size_t)brow * N + col0 + bcol;

    float4 a0 = *(const float4*)Aptr;
    float4 a1 = *(const float4*)(Aptr + (size_t)64 * K);
    float4 b0 = *(const float4*)Bptr;
    float4 b1 = *(const float4*)(Bptr + (size_t)8 * N);

    int KT = K >> 4;
    for (int kt = 0; kt < KT; ++kt) {
        As[acol+0][arow]    = a0.x; As[acol+1][arow]    = a0.y;
        As[acol+2][arow]    = a0.z; As[acol+3][arow]    = a0.w;
        As[acol+0][arow+64] = a1.x; As[acol+1][arow+64] = a1.y;
        As[acol+2][arow+64] = a1.z; As[acol+3][arow+64] = a1.w;
        *(float4*)&Bs[brow][bcol]     = b0;
        *(float4*)&Bs[brow + 8][bcol] = b1;
        __syncthreads();

        if (kt + 1 < KT) {
            Aptr += 16;
            Bptr += (size_t)16 * N;
            a0 = *(const float4*)Aptr;
            a1 = *(const float4*)(Aptr + (size_t)64 * K);
            b0 = *(const float4*)Bptr;
            b1 = *(const float4*)(Bptr + (size_t)8 * N);
        }

        #pragma unroll
        for (int k = 0; k < 16; ++k) {
            float ar[8], br[8];
            *(float4*)&ar[0] = *(const float4*)&As[k][ty * 8];
            *(float4*)&ar[4] = *(const float4*)&As[k][ty * 8 + 4];
            *(float4*)&br[0] = *(const float4*)&Bs[k][tx * 8];
            *(float4*)&br[4] = *(const float4*)&Bs[k][tx * 8 + 4];
            #pragma unroll
            for (int i = 0; i < 8; ++i)
                #pragma unroll
                for (int j = 0; j < 8; ++j)
                    acc[i][j] += ar[i] * br[j];
        }
        __syncthreads();
    }

    // epilogue
    #pragma unroll
    for (int i = 0; i < 8; ++i) {
        int r = row0 + ty * 8 + i;
        #pragma unroll
        for (int j4 = 0; j4 < 8; j4 += 4) {
            int c = col0 + tx * 8 + j4;
            float4 bv = *(const float4*)&bias[c];
            float4 o;
            o.x = acc[i][j4+0] + bv.x;
            o.y = acc[i][j4+1] + bv.y;
            o.z = acc[i][j4+2] + bv.z;
            o.w = acc[i][j4+3] + bv.w;
            if (EPI == 1) {
                float4 rv = *(const float4*)&res[(size_t)r * N + c];
                o.x += rv.x; o.y += rv.y; o.z += rv.z; o.w += rv.w;
            }
            if (EPI == 2) {
                o.x = gelu_f(o.x); o.y = gelu_f(o.y);
                o.z = gelu_f(o.z); o.w = gelu_f(o.w);
            }
            *(float4*)&C[(size_t)r * N + c] = o;
        }
    }
}

// ---------------- KV copy: qkv -> present region of d_out ------------------
// present[kv][b][h][l][hd] = qkv[(l*B+b)][(kv+1)*D + h*64 + hd]
__global__ void kvcopy_kernel(const float* __restrict__ qkv, float* __restrict__ present)
{
    int idx = blockIdx.x * blockDim.x + threadIdx.x;   // over float4s
    // idx = ((((kv*B + b)*H + h)*L + l)*16 + hd4)
    int hd4 = idx & 15;
    int l   = (idx >> 4) & (SEQ - 1);
    int h   = (idx >> 15) & (NH - 1);
    int b   = (idx >> 19) & (BATCH - 1);
    int kv  = idx >> 20;
    const float4* src = reinterpret_cast<const float4*>(
        qkv + (size_t)(l * BATCH + b) * (3 * DMODEL) + (size_t)(kv + 1) * DMODEL + h * HD) + hd4;
    reinterpret_cast<float4*>(present)[idx] = *src;
}

// ---------------- Flash attention fp32 -------------------------------------
// CTA: (64-query block, head, batch). 128 threads: 16 cols x 8 rows of threads,
// each thread owns 8 rows x 4 cols of the 64x64 S/P tile and 8x4 of O.
#define ATTN_SMEM ((64*64 + 64*68 + 64*64) * 4)

__global__ void __launch_bounds__(128)
attn_kernel(const float* __restrict__ qkv, const float* __restrict__ kvp,
            float* __restrict__ out)
{
    extern __shared__ float smem[];
    float* sQ = smem;                // 64 x 64
    float* sK = smem + 64 * 64;      // 64 x 68 (K transposed; reused as P)
    float* sV = sK + 64 * 68;        // 64 x 64

    int tid  = threadIdx.x;
    int tcol = tid & 15, trow = tid >> 4;
    int bq = blockIdx.x, h = blockIdx.y, b = blockIdx.z;

    // load Q tile, pre-scaled by 1/sqrt(HD)
    #pragma unroll
    for (int it = 0; it < 8; ++it) {
        int idx = it * 128 + tid;
        int r = idx >> 4, k4 = (idx & 15) * 4;
        int l = bq * 64 + r;
        float4 v = *(const float4*)(qkv + (size_t)(l * BATCH + b) * (3 * DMODEL) + h * HD + k4);
        const float sc = 0.125f;
        float4 o = make_float4(v.x * sc, v.y * sc, v.z * sc, v.w * sc);
        *(float4*)&sQ[r * 64 + k4] = o;
    }

    const float* Kg = kvp + ((size_t)b * NH + h) * SEQ * HD;
    const float* Vg = Kg + (size_t)BATCH * NH * SEQ * HD;

    float mrow[8], lrow[8], O[8][4];
    #pragma unroll
    for (int i = 0; i < 8; ++i) {
        mrow[i] = -1e30f; lrow[i] = 0.f;
        O[i][0] = O[i][1] = O[i][2] = O[i][3] = 0.f;
    }

    for (int kb = 0; kb < SEQ / 64; ++kb) {
        __syncthreads();   // prev P/V consumption done before overwrite
        // load K transposed: sK[k][c]
        #pragma unroll
        for (int it = 0; it < 8; ++it) {
            int idx = it * 128 + tid;
            int c = idx >> 4, k4 = (idx & 15) * 4;
            float4 v = *(const float4*)(Kg + (size_t)(kb * 64 + c) * HD + k4);
            sK[(k4 + 0) * 68 + c] = v.x;
            sK[(k4 + 1) * 68 + c] = v.y;
            sK[(k4 + 2) * 68 + c] = v.z;
            sK[(k4 + 3) * 68 + c] = v.w;
        }
        // load V: sV[c][d]
        #pragma unroll
        for (int it = 0; it < 8; ++it) {
            int idx = it * 128 + tid;
            int c = idx >> 4, d4 = (idx & 15) * 4;
            *(float4*)&sV[c * 64 + d4] = *(const float4*)(Vg + (size_t)(kb * 64 + c) * HD + d4);
        }
        __syncthreads();

        // S = Qs @ K^T   (S[i][j], rows i*8+trow, cols tcol*4+j)
        float S[8][4] = {};
        #pragma unroll
        for (int k = 0; k < 64; k += 4) {
            float4 k0 = *(const float4*)&sK[(k + 0) * 68 + tcol * 4];
            float4 k1 = *(const float4*)&sK[(k + 1) * 68 + tcol * 4];
            float4 k2 = *(const float4*)&sK[(k + 2) * 68 + tcol * 4];
            float4 k3 = *(const float4*)&sK[(k + 3) * 68 + tcol * 4];
            #pragma unroll
            for (int i = 0; i < 8; ++i) {
                float4 q = *(const float4*)&sQ[(i * 8 + trow) * 64 + k];
                S[i][0] += q.x * k0.x + q.y * k1.x + q.z * k2.x + q.w * k3.x;
                S[i][1] += q.x * k0.y + q.y * k1.y + q.z * k2.y + q.w * k3.y;
                S[i][2] += q.x * k0.z + q.y * k1.z + q.z * k2.z + q.w * k3.z;
                S[i][3] += q.x * k0.w + q.y * k1.w + q.z * k2.w + q.w * k3.w;
            }
        }

        // online softmax update
        #pragma unroll
        for (int i = 0; i < 8; ++i) {
            float mx = fmaxf(fmaxf(S[i][0], S[i][1]), fmaxf(S[i][2], S[i][3]));
            #pragma unroll
            for (int o = 1; o < 16; o <<= 1)
                mx = fmaxf(mx, __shfl_xor_sync(0xffffffffu, mx, o));
            float nm = fmaxf(mrow[i], mx);
            float corr = __expf(mrow[i] - nm);
            mrow[i] = nm;
            float p0 = __expf(S[i][0] - nm);
            float p1 = __expf(S[i][1] - nm);
            float p2 = __expf(S[i][2] - nm);
            float p3 = __expf(S[i][3] - nm);
            float rs = p0 + p1 + p2 + p3;
            #pragma unroll
            for (int o = 1; o < 16; o <<= 1)
                rs += __shfl_xor_sync(0xffffffffu, rs, o);
            lrow[i] = lrow[i] * corr + rs;
            O[i][0] *= corr; O[i][1] *= corr; O[i][2] *= corr; O[i][3] *= corr;
            S[i][0] = p0; S[i][1] = p1; S[i][2] = p2; S[i][3] = p3;
        }

        __syncthreads();   // everyone done reading sK (as K) before P store
        #pragma unroll
        for (int i = 0; i < 8; ++i)
            *(float4*)&sK[(i * 8 + trow) * 68 + tcol * 4] =
                make_float4(S[i][0], S[i][1], S[i][2], S[i][3]);
        __syncthreads();

        // O += P @ V
        #pragma unroll
        for (int c = 0; c < 64; c += 4) {
            float4 v0 = *(const float4*)&sV[(c + 0) * 64 + tcol * 4];
            float4 v1 = *(const float4*)&sV[(c + 1) * 64 + tcol * 4];
            float4 v2 = *(const float4*)&sV[(c + 2) * 64 + tcol * 4];
            float4 v3 = *(const float4*)&sV[(c + 3) * 64 + tcol * 4];
            #pragma unroll
            for (int i = 0; i < 8; ++i) {
                float4 p = *(const float4*)&sK[(i * 8 + trow) * 68 + c];
                O[i][0] += p.x * v0.x + p.y * v1.x + p.z * v2.x + p.w * v3.x;
                O[i][1] += p.x * v0.y + p.y * v1.y + p.z * v2.y + p.w * v3.y;
                O[i][2] += p.x * v0.z + p.y * v1.z + p.z * v2.z + p.w * v3.z;
                O[i][3] += p.x * v0.w + p.y * v1.w + p.z * v2.w + p.w * v3.w;
            }
        }
    }

    // write normalized output to g_attn in [L,B,D] layout
    #pragma unroll
    for (int i = 0; i < 8; ++i) {
        int r = i * 8 + trow;
        int l = bq * 64 + r;
        float inv = 1.0f / lrow[i];
        float4 o = make_float4(O[i][0] * inv, O[i][1] * inv, O[i][2] * inv, O[i][3] * inv);
        *(float4*)(out + (size_t)(l * BATCH + b) * DMODEL + h * HD + tcol * 4) = o;
    }
}

// ---------------- launcher --------------------------------------------------
extern "C" void kernel_launch(void* const* d_in, const int* in_sizes, int n_in,
                              void* d_out, int out_size)
{
    const float* x      = (const float*)d_in[0];
    const float* ln1_g  = (const float*)d_in[1];
    const float* ln1_b  = (const float*)d_in[2];
    const float* w_attn = (const float*)d_in[3];
    const float* b_attn = (const float*)d_in[4];
    const float* w_proj = (const float*)d_in[5];
    const float* b_proj = (const float*)d_in[6];
    const float* ln2_g  = (const float*)d_in[7];
    const float* ln2_b  = (const float*)d_in[8];
    const float* w_fc   = (const float*)d_in[9];
    const float* b_fc   = (const float*)d_in[10];
    const float* w_out  = (const float*)d_in[11];
    const float* b_out  = (const float*)d_in[12];

    float* out     = (float*)d_out;
    float* present = out + (size_t)SEQ * BATCH * DMODEL;

    float *h, *qkvp, *attnp, *x1, *h2, *mbuf;
    cudaGetSymbolAddress((void**)&h,     g_h);
    cudaGetSymbolAddress((void**)&qkvp,  g_qkv);
    cudaGetSymbolAddress((void**)&attnp, g_attn);
    cudaGetSymbolAddress((void**)&x1,    g_x1);
    cudaGetSymbolAddress((void**)&h2,    g_h2);
    cudaGetSymbolAddress((void**)&mbuf,  g_m);

    cudaFuncSetAttribute(attn_kernel, cudaFuncAttributeMaxDynamicSharedMemorySize, ATTN_SMEM);

    // 1. h = LN1(x)
    ln_kernel<<<ROWS, 256>>>(x, ln1_g, ln1_b, h);
    // 2. qkv = h @ w_attn + b_attn
    sgemm_kernel<0><<<dim3(3 * DMODEL / 128, ROWS / 128), 256>>>(
        h, w_attn, b_attn, nullptr, qkvp, ROWS, 3 * DMODEL, DMODEL);
    // 3. present (k, v) into d_out
    kvcopy_kernel<<<(2 * BATCH * NH * SEQ * 16) / 256, 256>>>(qkvp, present);
    // 4. attention -> attnp  [L,B,D]
    attn_kernel<<<dim3(SEQ / 64, NH, BATCH), 128, ATTN_SMEM>>>(qkvp, present, attnp);
    // 5. x1 = x + attnp @ w_proj + b_proj
    sgemm_kernel<1><<<dim3(DMODEL / 128, ROWS / 128), 256>>>(
        attnp, w_proj, b_proj, x, x1, ROWS, DMODEL, DMODEL);
    // 6. h2 = LN2(x1)
    ln_kernel<<<ROWS, 256>>>(x1, ln2_g, ln2_b, h2);
    // 7. m = gelu(h2 @ w_fc + b_fc)
    sgemm_kernel<2><<<dim3(DFF / 128, ROWS / 128), 256>>>(
        h2, w_fc, b_fc, nullptr, mbuf, ROWS, DFF, DMODEL);
    // 8. out_x = x1 + m @ w_out + b_out
    sgemm_kernel<1><<<dim3(DMODEL / 128, ROWS / 128), 256>>>(
        mbuf, w_out, b_out, x1, out, ROWS, DMODEL, DFF);
}

// round 4
// speedup vs baseline: 3.0749x; 3.0749x over previous
#include <cuda_runtime.h>
#include <math.h>

#define SEQ    2048
#define BATCH  2
#define DMODEL 1024
#define NH     16
#define HD     64
#define DFF    4096
#define ROWS   (SEQ*BATCH)   // 4096

// ---------------- scratch (device globals; no allocation allowed) ----------
__device__ float g_h   [ROWS*DMODEL];     // LN1 out
__device__ float g_qkv [ROWS*3*DMODEL];   // qkv
__device__ float g_attn[ROWS*DMODEL];     // attention out (pre-proj)
__device__ float g_x1  [ROWS*DMODEL];     // x + attn_proj
__device__ float g_h2  [ROWS*DMODEL];     // LN2 out
__device__ float g_m   [ROWS*DFF];        // gelu(fc) out

// ---------------- helpers ---------------------------------------------------
__device__ __forceinline__ float tf32r(float x)
{
    unsigned u;
    asm("cvt.rna.tf32.f32 %0, %1;" : "=r"(u) : "f"(x));
    return __uint_as_float(u);
}

__device__ __forceinline__ void mma8(float* c, const float* a, const float* b)
{
    asm volatile(
        "mma.sync.aligned.m16n8k8.row.col.f32.tf32.tf32.f32 "
        "{%0,%1,%2,%3}, {%4,%5,%6,%7}, {%8,%9}, {%0,%1,%2,%3};\n"
        : "+f"(c[0]), "+f"(c[1]), "+f"(c[2]), "+f"(c[3])
        : "r"(__float_as_uint(a[0])), "r"(__float_as_uint(a[1])),
          "r"(__float_as_uint(a[2])), "r"(__float_as_uint(a[3])),
          "r"(__float_as_uint(b[0])), "r"(__float_as_uint(b[1])));
}

__device__ __forceinline__ float4 cvt4(float4 v)
{
    return make_float4(tf32r(v.x), tf32r(v.y), tf32r(v.z), tf32r(v.w));
}

__device__ __forceinline__ float gelu_f(float v)
{
    float c = v + 0.044715f * v * v * v;
    return 0.5f * v * (1.0f + tanhf(0.7978845608028654f * c));
}

// ---------------- LayerNorm: one CTA per row, 256 threads, float4 ----------
__global__ void ln_kernel(const float* __restrict__ x,
                          const float* __restrict__ g,
                          const float* __restrict__ b,
                          float* __restrict__ y)
{
    int row = blockIdx.x;
    int tid = threadIdx.x;
    const float4* xr = reinterpret_cast<const float4*>(x + (size_t)row * DMODEL);
    float4 v = xr[tid];

    __shared__ float red[8];
    __shared__ float stat[2];

    float s = v.x + v.y + v.z + v.w;
    #pragma unroll
    for (int o = 16; o; o >>= 1) s += __shfl_xor_sync(0xffffffffu, s, o);
    if ((tid & 31) == 0) red[tid >> 5] = s;
    __syncthreads();
    if (tid == 0) {
        float t = 0.f;
        #pragma unroll
        for (int i = 0; i < 8; i++) t += red[i];
        stat[0] = t * (1.0f / DMODEL);
    }
    __syncthreads();
    float mu = stat[0];

    float dx = v.x - mu, dy = v.y - mu, dz = v.z - mu, dw = v.w - mu;
    float s2 = dx*dx + dy*dy + dz*dz + dw*dw;
    #pragma unroll
    for (int o = 16; o; o >>= 1) s2 += __shfl_xor_sync(0xffffffffu, s2, o);
    if ((tid & 31) == 0) red[tid >> 5] = s2;
    __syncthreads();
    if (tid == 0) {
        float t = 0.f;
        #pragma unroll
        for (int i = 0; i < 8; i++) t += red[i];
        stat[1] = rsqrtf(t * (1.0f / DMODEL) + 1e-5f);
    }
    __syncthreads();
    float rstd = stat[1];

    const float4* gr = reinterpret_cast<const float4*>(g);
    const float4* br = reinterpret_cast<const float4*>(b);
    float4 gv = gr[tid], bv = br[tid];
    float4 o;
    o.x = dx * rstd * gv.x + bv.x;
    o.y = dy * rstd * gv.y + bv.y;
    o.z = dz * rstd * gv.z + bv.z;
    o.w = dw * rstd * gv.w + bv.w;
    reinterpret_cast<float4*>(y + (size_t)row * DMODEL)[tid] = o;
}

// ---------------- TF32 tensor-core GEMM ------------------------------------
// C[M,N] = A[M,K] @ B[K,N] + epilogue.  BM=BN=128, BK=16, 256 threads (8 warps
// in a 2x4 grid, 64x32 per warp = 4 m-tiles x 4 n-tiles of m16n8k8).
// EPI: 0 = +bias, 1 = +bias+res, 2 = gelu(+bias)
#define APAD 20
#define BPAD 136

template<int EPI>
__global__ void __launch_bounds__(256, 2)
tgemm_kernel(const float* __restrict__ A, const float* __restrict__ B,
             const float* __restrict__ bias, const float* __restrict__ res,
             float* __restrict__ C, int M, int N, int K)
{
    __shared__ float As[128][APAD];   // [m][k] tf32
    __shared__ float Bs[16][BPAD];    // [k][n] tf32

    int tid  = threadIdx.x;
    int warp = tid >> 5, lane = tid & 31;
    int lr = lane >> 2, lc = lane & 3;
    int wm = warp >> 2, wn = warp & 3;               // 2 x 4 warp grid
    int row0 = blockIdx.y * 128, col0 = blockIdx.x * 128;

    float acc[4][4][4];
    #pragma unroll
    for (int i = 0; i < 4; ++i)
        #pragma unroll
        for (int j = 0; j < 4; ++j)
            acc[i][j][0] = acc[i][j][1] = acc[i][j][2] = acc[i][j][3] = 0.f;

    int arow = tid >> 2;            // 0..63
    int acol = (tid & 3) * 4;       // 0,4,8,12
    int brow = tid >> 5;            // 0..7
    int bcol = lane * 4;            // 0..124

    const float* Aptr = A + (size_t)(row0 + arow) * K + acol;
    const float* Bptr = B + (size_t)brow * N + col0 + bcol;

    float4 a0 = *(const float4*)Aptr;
    float4 a1 = *(const float4*)(Aptr + (size_t)64 * K);
    float4 b0 = *(const float4*)Bptr;
    float4 b1 = *(const float4*)(Bptr + (size_t)8 * N);

    int KT = K >> 4;
    for (int kt = 0; kt < KT; ++kt) {
        *(float4*)&As[arow][acol]      = cvt4(a0);
        *(float4*)&As[arow + 64][acol] = cvt4(a1);
        *(float4*)&Bs[brow][bcol]      = cvt4(b0);
        *(float4*)&Bs[brow + 8][bcol]  = cvt4(b1);
        __syncthreads();

        if (kt + 1 < KT) {
            Aptr += 16;
            Bptr += (size_t)16 * N;
            a0 = *(const float4*)Aptr;
            a1 = *(const float4*)(Aptr + (size_t)64 * K);
            b0 = *(const float4*)Bptr;
            b1 = *(const float4*)(Bptr + (size_t)8 * N);
        }

        #pragma unroll
        for (int kk = 0; kk < 2; ++kk) {
            int k = kk * 8;
            float af[4][4], bf[4][2];
            #pragma unroll
            for (int mi = 0; mi < 4; ++mi) {
                int r = wm * 64 + mi * 16 + lr;
                af[mi][0] = As[r][k + lc];
                af[mi][1] = As[r + 8][k + lc];
                af[mi][2] = As[r][k + 4 + lc];
                af[mi][3] = As[r + 8][k + 4 + lc];
            }
            #pragma unroll
            for (int ni = 0; ni < 4; ++ni) {
                int c = wn * 32 + ni * 8 + lr;
                bf[ni][0] = Bs[k + lc][c];
                bf[ni][1] = Bs[k + 4 + lc][c];
            }
            #pragma unroll
            for (int mi = 0; mi < 4; ++mi)
                #pragma unroll
                for (int ni = 0; ni < 4; ++ni)
                    mma8(acc[mi][ni], af[mi], bf[ni]);
        }
        __syncthreads();
    }

    // epilogue: C-frag row = base+lr (+8), col = base + 2*lc (+1)
    #pragma unroll
    for (int mi = 0; mi < 4; ++mi) {
        #pragma unroll
        for (int hh = 0; hh < 2; ++hh) {
            int r = row0 + wm * 64 + mi * 16 + lr + hh * 8;
            #pragma unroll
            for (int ni = 0; ni < 4; ++ni) {
                int c = col0 + wn * 32 + ni * 8 + 2 * lc;
                float2 bv = *(const float2*)&bias[c];
                float2 o;
                o.x = acc[mi][ni][2 * hh + 0] + bv.x;
                o.y = acc[mi][ni][2 * hh + 1] + bv.y;
                if (EPI == 1) {
                    float2 rv = *(const float2*)&res[(size_t)r * N + c];
                    o.x += rv.x; o.y += rv.y;
                }
                if (EPI == 2) {
                    o.x = gelu_f(o.x); o.y = gelu_f(o.y);
                }
                *(float2*)&C[(size_t)r * N + c] = o;
            }
        }
    }
}

// ---------------- KV copy: qkv -> present region of d_out ------------------
__global__ void kvcopy_kernel(const float* __restrict__ qkv, float* __restrict__ present)
{
    int idx = blockIdx.x * blockDim.x + threadIdx.x;   // over float4s
    int hd4 = idx & 15;
    int l   = (idx >> 4) & (SEQ - 1);
    int h   = (idx >> 15) & (NH - 1);
    int b   = (idx >> 19) & (BATCH - 1);
    int kv  = idx >> 20;
    const float4* src = reinterpret_cast<const float4*>(
        qkv + (size_t)(l * BATCH + b) * (3 * DMODEL) + (size_t)(kv + 1) * DMODEL + h * HD) + hd4;
    reinterpret_cast<float4*>(present)[idx] = *src;
}

// ---------------- Flash attention (TF32 tensor cores) ----------------------
// CTA: (64-query block, head, batch), 128 threads = 4 warps; warp w owns query
// rows 16w..16w+15. S and P@V via mma.m16n8k8 tf32. Q fragments live in regs;
// P reuses the Q smem tile (each warp touches only its own 16 rows).
#define KPAD 68
#define VPAD 72
#define ATTN_SMEM ((64*KPAD + 64*KPAD + 64*VPAD) * 4)

__global__ void __launch_bounds__(128)
attn_kernel(const float* __restrict__ qkv, const float* __restrict__ kvp,
            float* __restrict__ out)
{
    extern __shared__ float smem[];
    float* sQ = smem;                  // 64 x KPAD (tf32; reused as sP)
    float* sK = smem + 64 * KPAD;      // 64 x KPAD (tf32)
    float* sV = sK + 64 * KPAD;        // 64 x VPAD (tf32)

    int tid  = threadIdx.x;
    int w = tid >> 5, lane = tid & 31;
    int lr = lane >> 2, lc = lane & 3;
    int bq = blockIdx.x, h = blockIdx.y, b = blockIdx.z;

    // stage Q tile (pre-scaled by 1/sqrt(HD), tf32)
    #pragma unroll
    for (int it = 0; it < 8; ++it) {
        int idx = it * 128 + tid;
        int r = idx >> 4, c4 = (idx & 15) * 4;
        int l = bq * 64 + r;
        float4 v = *(const float4*)(qkv + (size_t)(l * BATCH + b) * (3 * DMODEL) + h * HD + c4);
        *(float4*)&sQ[r * KPAD + c4] = make_float4(
            tf32r(v.x * 0.125f), tf32r(v.y * 0.125f),
            tf32r(v.z * 0.125f), tf32r(v.w * 0.125f));
    }
    __syncthreads();

    // preload Q fragments (rows 16w..16w+15, all 8 k-steps)
    float qf[8][4];
    {
        int row = w * 16 + lr;
        #pragma unroll
        for (int ks = 0; ks < 8; ++ks) {
            qf[ks][0] = sQ[row * KPAD + ks * 8 + lc];
            qf[ks][1] = sQ[(row + 8) * KPAD + ks * 8 + lc];
            qf[ks][2] = sQ[row * KPAD + ks * 8 + 4 + lc];
            qf[ks][3] = sQ[(row + 8) * KPAD + ks * 8 + 4 + lc];
        }
    }
    float* sP = sQ;   // safe: warp reads/writes only its own 16 rows hereafter

    const float* Kg = kvp + ((size_t)b * NH + h) * SEQ * HD;
    const float* Vg = Kg + (size_t)BATCH * NH * SEQ * HD;

    float mrow[2] = {-1e30f, -1e30f};
    float lrow[2] = {0.f, 0.f};
    float O[8][4];
    #pragma unroll
    for (int ni = 0; ni < 8; ++ni)
        O[ni][0] = O[ni][1] = O[ni][2] = O[ni][3] = 0.f;

    for (int kb = 0; kb < SEQ / 64; ++kb) {
        __syncthreads();   // prior iter's sK/sV reads done
        #pragma unroll
        for (int it = 0; it < 8; ++it) {
            int idx = it * 128 + tid;
            int r = idx >> 4, c4 = (idx & 15) * 4;
            float4 kv4 = *(const float4*)(Kg + (size_t)(kb * 64 + r) * HD + c4);
            *(float4*)&sK[r * KPAD + c4] = cvt4(kv4);
            float4 vv4 = *(const float4*)(Vg + (size_t)(kb * 64 + r) * HD + c4);
            *(float4*)&sV[r * VPAD + c4] = cvt4(vv4);
        }
        __syncthreads();

        // S = Q @ K^T : warp computes 16 x 64 (8 n-tiles)
        float S[8][4];
        #pragma unroll
        for (int ni = 0; ni < 8; ++ni)
            S[ni][0] = S[ni][1] = S[ni][2] = S[ni][3] = 0.f;
        #pragma unroll
        for (int ks = 0; ks < 8; ++ks) {
            #pragma unroll
            for (int ni = 0; ni < 8; ++ni) {
                float bf[2];
                bf[0] = sK[(ni * 8 + lr) * KPAD + ks * 8 + lc];
                bf[1] = sK[(ni * 8 + lr) * KPAD + ks * 8 + 4 + lc];
                mma8(S[ni], qf[ks], bf);
            }
        }

        // online softmax (row r = 16w+lr for hh=0, +8 for hh=1; rows span quad lanes)
        #pragma unroll
        for (int hh = 0; hh < 2; ++hh) {
            float mx = -1e30f;
            #pragma unroll
            for (int ni = 0; ni < 8; ++ni)
                mx = fmaxf(mx, fmaxf(S[ni][2*hh], S[ni][2*hh+1]));
            mx = fmaxf(mx, __shfl_xor_sync(0xffffffffu, mx, 1));
            mx = fmaxf(mx, __shfl_xor_sync(0xffffffffu, mx, 2));
            float nm = fmaxf(mrow[hh], mx);
            float corr = __expf(mrow[hh] - nm);
            mrow[hh] = nm;
            float rs = 0.f;
            #pragma unroll
            for (int ni = 0; ni < 8; ++ni) {
                float p0 = __expf(S[ni][2*hh]   - nm);
                float p1 = __expf(S[ni][2*hh+1] - nm);
                S[ni][2*hh] = p0; S[ni][2*hh+1] = p1;
                rs += p0 + p1;
            }
            rs += __shfl_xor_sync(0xffffffffu, rs, 1);
            rs += __shfl_xor_sync(0xffffffffu, rs, 2);
            lrow[hh] = lrow[hh] * corr + rs;
            #pragma unroll
            for (int ni = 0; ni < 8; ++ni) {
                O[ni][2*hh]   *= corr;
                O[ni][2*hh+1] *= corr;
            }
        }

        // store P (tf32) into warp-private rows of sP
        __syncwarp();
        {
            int row = w * 16 + lr;
            #pragma unroll
            for (int ni = 0; ni < 8; ++ni) {
                int col = ni * 8 + 2 * lc;
                *(float2*)&sP[row * KPAD + col] =
                    make_float2(tf32r(S[ni][0]), tf32r(S[ni][1]));
                *(float2*)&sP[(row + 8) * KPAD + col] =
                    make_float2(tf32r(S[ni][2]), tf32r(S[ni][3]));
            }
        }
        __syncwarp();

        // O += P @ V
        #pragma unroll
        for (int ks = 0; ks < 8; ++ks) {
            float af[4];
            int row = w * 16 + lr;
            af[0] = sP[row * KPAD + ks * 8 + lc];
            af[1] = sP[(row + 8) * KPAD + ks * 8 + lc];
            af[2] = sP[row * KPAD + ks * 8 + 4 + lc];
            af[3] = sP[(row + 8) * KPAD + ks * 8 + 4 + lc];
            #pragma unroll
            for (int ni = 0; ni < 8; ++ni) {
                float bf[2];
                bf[0] = sV[(ks * 8 + lc) * VPAD + ni * 8 + lr];
                bf[1] = sV[(ks * 8 + lc + 4) * VPAD + ni * 8 + lr];
                mma8(O[ni], af, bf);
            }
        }
    }

    // normalized output, [L,B,D] layout
    #pragma unroll
    for (int hh = 0; hh < 2; ++hh) {
        int r = w * 16 + lr + hh * 8;
        int l = bq * 64 + r;
        float inv = 1.0f / lrow[hh];
        float* po = out + (size_t)(l * BATCH + b) * DMODEL + h * HD;
        #pragma unroll
        for (int ni = 0; ni < 8; ++ni)
            *(float2*)&po[ni * 8 + 2 * lc] =
                make_float2(O[ni][2*hh] * inv, O[ni][2*hh+1] * inv);
    }
}

// ---------------- launcher --------------------------------------------------
extern "C" void kernel_launch(void* const* d_in, const int* in_sizes, int n_in,
                              void* d_out, int out_size)
{
    const float* x      = (const float*)d_in[0];
    const float* ln1_g  = (const float*)d_in[1];
    const float* ln1_b  = (const float*)d_in[2];
    const float* w_attn = (const float*)d_in[3];
    const float* b_attn = (const float*)d_in[4];
    const float* w_proj = (const float*)d_in[5];
    const float* b_proj = (const float*)d_in[6];
    const float* ln2_g  = (const float*)d_in[7];
    const float* ln2_b  = (const float*)d_in[8];
    const float* w_fc   = (const float*)d_in[9];
    const float* b_fc   = (const float*)d_in[10];
    const float* w_out  = (const float*)d_in[11];
    const float* b_out  = (const float*)d_in[12];

    float* out     = (float*)d_out;
    float* present = out + (size_t)SEQ * BATCH * DMODEL;

    float *h, *qkvp, *attnp, *x1, *h2, *mbuf;
    cudaGetSymbolAddress((void**)&h,     g_h);
    cudaGetSymbolAddress((void**)&qkvp,  g_qkv);
    cudaGetSymbolAddress((void**)&attnp, g_attn);
    cudaGetSymbolAddress((void**)&x1,    g_x1);
    cudaGetSymbolAddress((void**)&h2,    g_h2);
    cudaGetSymbolAddress((void**)&mbuf,  g_m);

    cudaFuncSetAttribute(attn_kernel, cudaFuncAttributeMaxDynamicSharedMemorySize, ATTN_SMEM);

    // 1. h = LN1(x)
    ln_kernel<<<ROWS, 256>>>(x, ln1_g, ln1_b, h);
    // 2. qkv = h @ w_attn + b_attn
    tgemm_kernel<0><<<dim3(3 * DMODEL / 128, ROWS / 128), 256>>>(
        h, w_attn, b_attn, nullptr, qkvp, ROWS, 3 * DMODEL, DMODEL);
    // 3. present (k, v) into d_out
    kvcopy_kernel<<<(2 * BATCH * NH * SEQ * 16) / 256, 256>>>(qkvp, present);
    // 4. attention -> attnp  [L,B,D]
    attn_kernel<<<dim3(SEQ / 64, NH, BATCH), 128, ATTN_SMEM>>>(qkvp, present, attnp);
    // 5. x1 = x + attnp @ w_proj + b_proj
    tgemm_kernel<1><<<dim3(DMODEL / 128, ROWS / 128), 256>>>(
        attnp, w_proj, b_proj, x, x1, ROWS, DMODEL, DMODEL);
    // 6. h2 = LN2(x1)
    ln_kernel<<<ROWS, 256>>>(x1, ln2_g, ln2_b, h2);
    // 7. m = gelu(h2 @ w_fc + b_fc)
    tgemm_kernel<2><<<dim3(DFF / 128, ROWS / 128), 256>>>(
        h2, w_fc, b_fc, nullptr, mbuf, ROWS, DFF, DMODEL);
    // 8. out_x = x1 + m @ w_out + b_out
    tgemm_kernel<1><<<dim3(DMODEL / 128, ROWS / 128), 256>>>(
        mbuf, w_out, b_out, x1, out, ROWS, DMODEL, DFF);
}

// round 7
// speedup vs baseline: 4.0649x; 1.3220x over previous
#include <cuda_runtime.h>
#include <cuda_fp16.h>
#include <math.h>
#include <stdint.h>

#define SEQ    2048
#define BATCH  2
#define DMODEL 1024
#define NH     16
#define HD     64
#define DFF    4096
#define ROWS   (SEQ*BATCH)   // 4096

// ---------------- scratch (device globals; no allocation allowed) ----------
__device__ __half g_h16  [ROWS*DMODEL];      // LN1 out (fp16)
__device__ float  g_qkv  [ROWS*3*DMODEL];    // qkv (fp32)
__device__ __half g_attn16[ROWS*DMODEL];     // attention out (fp16)
__device__ float  g_x1   [ROWS*DMODEL];      // x + attn_proj (fp32)
__device__ __half g_h2_16[ROWS*DMODEL];      // LN2 out (fp16)
__device__ __half g_m16  [ROWS*DFF];         // gelu(fc) out (fp16)
// transposed fp16 weights [N,K]
__device__ __half g_wt_attn[3*DMODEL*DMODEL];
__device__ __half g_wt_proj[DMODEL*DMODEL];
__device__ __half g_wt_fc  [DFF*DMODEL];
__device__ __half g_wt_out [DMODEL*DFF];

// ---------------- helpers ----------------------------------------------------
__device__ __forceinline__ uint32_t smem_u32(const void* p)
{
    return (uint32_t)__cvta_generic_to_shared(p);
}

__device__ __forceinline__ void cp16(uint32_t dst, const void* src)
{
    asm volatile("cp.async.cg.shared.global [%0], [%1], 16;" :: "r"(dst), "l"(src) : "memory");
}

__device__ __forceinline__ void ldsm_x4(uint32_t* r, uint32_t addr)
{
    asm volatile("ldmatrix.sync.aligned.m8n8.x4.shared.b16 {%0,%1,%2,%3}, [%4];"
                 : "=r"(r[0]), "=r"(r[1]), "=r"(r[2]), "=r"(r[3]) : "r"(addr));
}

__device__ __forceinline__ void ldsm_x2(uint32_t* r, uint32_t addr)
{
    asm volatile("ldmatrix.sync.aligned.m8n8.x2.shared.b16 {%0,%1}, [%2];"
                 : "=r"(r[0]), "=r"(r[1]) : "r"(addr));
}

__device__ __forceinline__ void mma16816(float* c, const uint32_t* a, const uint32_t* b)
{
    asm volatile(
        "mma.sync.aligned.m16n8k16.row.col.f32.f16.f16.f32 "
        "{%0,%1,%2,%3}, {%4,%5,%6,%7}, {%8,%9}, {%0,%1,%2,%3};\n"
        : "+f"(c[0]), "+f"(c[1]), "+f"(c[2]), "+f"(c[3])
        : "r"(a[0]), "r"(a[1]), "r"(a[2]), "r"(a[3]),
          "r"(b[0]), "r"(b[1]));
}

__device__ __forceinline__ float tf32r(float x)
{
    unsigned u;
    asm("cvt.rna.tf32.f32 %0, %1;" : "=r"(u) : "f"(x));
    return __uint_as_float(u);
}

__device__ __forceinline__ void mma8(float* c, const float* a, const float* b)
{
    asm volatile(
        "mma.sync.aligned.m16n8k8.row.col.f32.tf32.tf32.f32 "
        "{%0,%1,%2,%3}, {%4,%5,%6,%7}, {%8,%9}, {%0,%1,%2,%3};\n"
        : "+f"(c[0]), "+f"(c[1]), "+f"(c[2]), "+f"(c[3])
        : "r"(__float_as_uint(a[0])), "r"(__float_as_uint(a[1])),
          "r"(__float_as_uint(a[2])), "r"(__float_as_uint(a[3])),
          "r"(__float_as_uint(b[0])), "r"(__float_as_uint(b[1])));
}

__device__ __forceinline__ float4 cvt4(float4 v)
{
    return make_float4(tf32r(v.x), tf32r(v.y), tf32r(v.z), tf32r(v.w));
}

__device__ __forceinline__ float gelu_f(float v)
{
    float c = v + 0.044715f * v * v * v;
    return 0.5f * v * (1.0f + tanhf(0.7978845608028654f * c));
}

// ---------------- weight transpose+convert: W[K,N] f32 -> Wt[N,K] f16 ------
__global__ void transpose_w(const float* __restrict__ W, __half* __restrict__ Wt,
                            int K, int N)
{
    __shared__ float t[32][33];
    int n0 = blockIdx.x * 32, k0 = blockIdx.y * 32;
    int tx = threadIdx.x, ty = threadIdx.y;
    #pragma unroll
    for (int d = 0; d < 32; d += 8)
        t[ty + d][tx] = W[(size_t)(k0 + ty + d) * N + n0 + tx];
    __syncthreads();
    #pragma unroll
    for (int d = 0; d < 32; d += 8)
        Wt[(size_t)(n0 + ty + d) * K + k0 + tx] = __float2half_rn(t[tx][ty + d]);
}

// ---------------- LayerNorm: one CTA per row, fp16 output ------------------
__global__ void ln_kernel(const float* __restrict__ x,
                          const float* __restrict__ g,
                          const float* __restrict__ b,
                          __half* __restrict__ y)
{
    int row = blockIdx.x;
    int tid = threadIdx.x;
    const float4* xr = reinterpret_cast<const float4*>(x + (size_t)row * DMODEL);
    float4 v = xr[tid];

    __shared__ float red[8];
    __shared__ float stat[2];

    float s = v.x + v.y + v.z + v.w;
    #pragma unroll
    for (int o = 16; o; o >>= 1) s += __shfl_xor_sync(0xffffffffu, s, o);
    if ((tid & 31) == 0) red[tid >> 5] = s;
    __syncthreads();
    if (tid == 0) {
        float t = 0.f;
        #pragma unroll
        for (int i = 0; i < 8; i++) t += red[i];
        stat[0] = t * (1.0f / DMODEL);
    }
    __syncthreads();
    float mu = stat[0];

    float dx = v.x - mu, dy = v.y - mu, dz = v.z - mu, dw = v.w - mu;
    float s2 = dx*dx + dy*dy + dz*dz + dw*dw;
    #pragma unroll
    for (int o = 16; o; o >>= 1) s2 += __shfl_xor_sync(0xffffffffu, s2, o);
    if ((tid & 31) == 0) red[tid >> 5] = s2;
    __syncthreads();
    if (tid == 0) {
        float t = 0.f;
        #pragma unroll
        for (int i = 0; i < 8; i++) t += red[i];
        stat[1] = rsqrtf(t * (1.0f / DMODEL) + 1e-5f);
    }
    __syncthreads();
    float rstd = stat[1];

    const float4* gr = reinterpret_cast<const float4*>(g);
    const float4* br = reinterpret_cast<const float4*>(b);
    float4 gv = gr[tid], bv = br[tid];
    __half2 p0 = __floats2half2_rn(dx * rstd * gv.x + bv.x, dy * rstd * gv.y + bv.y);
    __half2 p1 = __floats2half2_rn(dz * rstd * gv.z + bv.z, dw * rstd * gv.w + bv.w);
    __half2* yr = reinterpret_cast<__half2*>(y + (size_t)row * DMODEL);
    yr[tid * 2 + 0] = p0;
    yr[tid * 2 + 1] = p1;
}

// ---------------- fp16 mma.sync GEMM ----------------------------------------
// C[M,N] = A[M,K]f16 @ Bt[N,K]f16^T + epilogue, fp32 accum.
// 128x128 tile, BK=32 halves, 4-stage cp.async ring, ldmatrix fragments.
// 256 threads = 8 warps in 2x4; warp tile 64x32 = 4x4 m16n8k16.
// EPI: 0 = +bias (f32 out), 1 = +bias+res (f32 out), 2 = gelu(+bias) (f16 out)
#define BK        32
#define KROW      40                        // BK + 8 pad (halves); 80B stride
#define A_STAGE_H (128*KROW)                // halves
#define STAGE_B   (2*A_STAGE_H*2)           // A + B bytes = 20480
#define GSTAGES   4
#define GEMM_SMEM (GSTAGES*STAGE_B)         // 81920

template<int EPI>
__global__ void __launch_bounds__(256, 1)
hgemm(const __half* __restrict__ A, const __half* __restrict__ Bt,
      const float* __restrict__ bias, const float* __restrict__ res,
      float* __restrict__ Cf, __half* __restrict__ Ch,
      int M, int N, int K)
{
    extern __shared__ char smem_raw[];
    uint32_t sbase = smem_u32(smem_raw);

    int tid = threadIdx.x;
    int w = tid >> 5, lane = tid & 31;
    int lr = lane >> 2, lc = lane & 3;
    int wm = w >> 2, wn = w & 3;
    int row0 = blockIdx.y * 128, col0 = blockIdx.x * 128;
    int KT = K / BK;

    float acc[4][4][4];
    #pragma unroll
    for (int i = 0; i < 4; ++i)
        #pragma unroll
        for (int j = 0; j < 4; ++j)
            acc[i][j][0] = acc[i][j][1] = acc[i][j][2] = acc[i][j][3] = 0.f;

    // load mapping: 512 16B-chunks per operand per stage; thread does chunks
    // tid and tid+256.  chunk c: row = c>>2, seg = c&3 (16B = 8 halves).
    int r0 = tid >> 2, s0 = (tid & 3);          // chunk tid
    int r1 = (tid + 256) >> 2, s1 = (tid & 3);  // chunk tid+256 (seg same: +256 = +64 rows)
    const char* Asrc0 = (const char*)(A + (size_t)(row0 + r0) * K + s0 * 8);
    const char* Asrc1 = (const char*)(A + (size_t)(row0 + r1) * K + s1 * 8);
    const char* Bsrc0 = (const char*)(Bt + (size_t)(col0 + r0) * K + s0 * 8);
    const char* Bsrc1 = (const char*)(Bt + (size_t)(col0 + r1) * K + s1 * 8);
    uint32_t dA0 = (uint32_t)(r0 * KROW + s0 * 8) * 2;
    uint32_t dA1 = (uint32_t)(r1 * KROW + s1 * 8) * 2;

    // fragment smem addresses (within a stage)
    // A: row = wm*64 + mi*16 + (lane&15), col = kk*16 + (lane>>4)*8
    // B: row = wn*32 + ni*8 + (lane&7), col = kk*16 + ((lane>>3)&1)*8
    uint32_t aFrag[2], bFrag[2];
    #pragma unroll
    for (int kk = 0; kk < 2; ++kk) {
        aFrag[kk] = (uint32_t)((wm * 64 + (lane & 15)) * KROW + kk * 16 + (lane >> 4) * 8) * 2;
        bFrag[kk] = (uint32_t)(A_STAGE_H * 2) +
                    (uint32_t)((wn * 32 + (lane & 7)) * KROW + kk * 16 + ((lane >> 3) & 1) * 8) * 2;
    }

    auto load_stage = [&](int slot, int kc) {
        uint32_t ab = sbase + slot * STAGE_B;
        uint32_t bb = ab + A_STAGE_H * 2;
        size_t koff = (size_t)kc * BK * 2;   // bytes
        cp16(ab + dA0, Asrc0 + koff);
        cp16(ab + dA1, Asrc1 + koff);
        cp16(bb + dA0, Bsrc0 + koff);
        cp16(bb + dA1, Bsrc1 + koff);
    };

    // prologue: stages 0..2
    #pragma unroll
    for (int c = 0; c < GSTAGES - 1; ++c) {
        load_stage(c, c);
        asm volatile("cp.async.commit_group;" ::: "memory");
    }

    for (int i = 0; i < KT; ++i) {
        asm volatile("cp.async.wait_group %0;" :: "n"(GSTAGES - 2) : "memory");
        __syncthreads();

        if (i + GSTAGES - 1 < KT)
            load_stage((i + GSTAGES - 1) & (GSTAGES - 1), i + GSTAGES - 1);
        asm volatile("cp.async.commit_group;" ::: "memory");

        uint32_t stg = sbase + (i & (GSTAGES - 1)) * STAGE_B;
        #pragma unroll
        for (int kk = 0; kk < 2; ++kk) {
            uint32_t af[4][4], bf[4][2];
            #pragma unroll
            for (int mi = 0; mi < 4; ++mi)
                ldsm_x4(af[mi], stg + aFrag[kk] + (uint32_t)(mi * 16 * KROW) * 2);
            #pragma unroll
            for (int ni = 0; ni < 4; ++ni)
                ldsm_x2(bf[ni], stg + bFrag[kk] + (uint32_t)(ni * 8 * KROW) * 2);
            #pragma unroll
            for (int mi = 0; mi < 4; ++mi)
                #pragma unroll
                for (int ni = 0; ni < 4; ++ni)
                    mma16816(acc[mi][ni], af[mi], bf[ni]);
        }
        __syncthreads();
    }

    // epilogue: C-frag row = base+lr (+8), col = base + 2*lc (+1)
    #pragma unroll
    for (int mi = 0; mi < 4; ++mi) {
        #pragma unroll
        for (int hh = 0; hh < 2; ++hh) {
            int r = row0 + wm * 64 + mi * 16 + lr + hh * 8;
            #pragma unroll
            for (int ni = 0; ni < 4; ++ni) {
                int c = col0 + wn * 32 + ni * 8 + 2 * lc;
                float2 bv = *(const float2*)&bias[c];
                float ox = acc[mi][ni][2 * hh + 0] + bv.x;
                float oy = acc[mi][ni][2 * hh + 1] + bv.y;
                if (EPI == 1) {
                    float2 rv = *(const float2*)&res[(size_t)r * N + c];
                    ox += rv.x; oy += rv.y;
                }
                if (EPI == 2) {
                    *(__half2*)&Ch[(size_t)r * N + c] =
                        __floats2half2_rn(gelu_f(ox), gelu_f(oy));
                } else {
                    *(float2*)&Cf[(size_t)r * N + c] = make_float2(ox, oy);
                }
            }
        }
    }
}

// ---------------- KV copy: qkv -> present region of d_out ------------------
__global__ void kvcopy_kernel(const float* __restrict__ qkv, float* __restrict__ present)
{
    int idx = blockIdx.x * blockDim.x + threadIdx.x;   // over float4s
    int hd4 = idx & 15;
    int l   = (idx >> 4) & (SEQ - 1);
    int h   = (idx >> 15) & (NH - 1);
    int b   = (idx >> 19) & (BATCH - 1);
    int kv  = idx >> 20;
    const float4* src = reinterpret_cast<const float4*>(
        qkv + (size_t)(l * BATCH + b) * (3 * DMODEL) + (size_t)(kv + 1) * DMODEL + h * HD) + hd4;
    reinterpret_cast<float4*>(present)[idx] = *src;
}

// ---------------- Flash attention (TF32 mma.sync) --------------------------
// CTA: 128 queries x (head, batch), 256 threads = 8 warps; warp w owns rows
// 16w..16w+15. Output written as fp16 (feeds proj GEMM).
#define KPAD 68
#define VPAD 72
#define QROWS 128
#define ATTN_SMEM ((QROWS*KPAD + 64*KPAD + 64*VPAD) * 4)

__global__ void __launch_bounds__(256)
attn_kernel(const float* __restrict__ qkv, const float* __restrict__ kvp,
            __half* __restrict__ out)
{
    extern __shared__ float smem[];
    float* sQ = smem;                   // QROWS x KPAD (tf32; reused as sP)
    float* sK = smem + QROWS * KPAD;    // 64 x KPAD
    float* sV = sK + 64 * KPAD;         // 64 x VPAD

    int tid  = threadIdx.x;
    int w = tid >> 5, lane = tid & 31;
    int lr = lane >> 2, lc = lane & 3;
    int bq = blockIdx.x, h = blockIdx.y, b = blockIdx.z;

    // stage Q tile (pre-scaled by 1/sqrt(HD), tf32): 128 rows x 64
    #pragma unroll
    for (int it = 0; it < 8; ++it) {
        int idx = it * 256 + tid;
        int r = idx >> 4, c4 = (idx & 15) * 4;
        int l = bq * QROWS + r;
        float4 v = *(const float4*)(qkv + (size_t)(l * BATCH + b) * (3 * DMODEL) + h * HD + c4);
        *(float4*)&sQ[r * KPAD + c4] = make_float4(
            tf32r(v.x * 0.125f), tf32r(v.y * 0.125f),
            tf32r(v.z * 0.125f), tf32r(v.w * 0.125f));
    }
    __syncthreads();

    // preload Q fragments (rows 16w..16w+15, all 8 k-steps)
    float qf[8][4];
    {
        int row = w * 16 + lr;
        #pragma unroll
        for (int ks = 0; ks < 8; ++ks) {
            qf[ks][0] = sQ[row * KPAD + ks * 8 + lc];
            qf[ks][1] = sQ[(row + 8) * KPAD + ks * 8 + lc];
            qf[ks][2] = sQ[row * KPAD + ks * 8 + 4 + lc];
            qf[ks][3] = sQ[(row + 8) * KPAD + ks * 8 + 4 + lc];
        }
    }
    float* sP = sQ;   // safe: warp reads/writes only its own 16 rows hereafter

    const float* Kg = kvp + ((size_t)b * NH + h) * SEQ * HD;
    const float* Vg = Kg + (size_t)BATCH * NH * SEQ * HD;

    float mrow[2] = {-1e30f, -1e30f};
    float lrow[2] = {0.f, 0.f};
    float O[8][4];
    #pragma unroll
    for (int ni = 0; ni < 8; ++ni)
        O[ni][0] = O[ni][1] = O[ni][2] = O[ni][3] = 0.f;

    for (int kb = 0; kb < SEQ / 64; ++kb) {
        __syncthreads();   // prior iter's sK/sV reads done
        #pragma unroll
        for (int it = 0; it < 4; ++it) {
            int idx = it * 256 + tid;
            int r = idx >> 4, c4 = (idx & 15) * 4;
            float4 kv4 = *(const float4*)(Kg + (size_t)(kb * 64 + r) * HD + c4);
            *(float4*)&sK[r * KPAD + c4] = cvt4(kv4);
            float4 vv4 = *(const float4*)(Vg + (size_t)(kb * 64 + r) * HD + c4);
            *(float4*)&sV[r * VPAD + c4] = cvt4(vv4);
        }
        __syncthreads();

        // S = Q @ K^T : warp computes 16 x 64 (8 n-tiles)
        float S[8][4];
        #pragma unroll
        for (int ni = 0; ni < 8; ++ni)
            S[ni][0] = S[ni][1] = S[ni][2] = S[ni][3] = 0.f;
        #pragma unroll
        for (int ks = 0; ks < 8; ++ks) {
            #pragma unroll
            for (int ni = 0; ni < 8; ++ni) {
                float bf[2];
                bf[0] = sK[(ni * 8 + lr) * KPAD + ks * 8 + lc];
                bf[1] = sK[(ni * 8 + lr) * KPAD + ks * 8 + 4 + lc];
                mma8(S[ni], qf[ks], bf);
            }
        }

        // online softmax
        #pragma unroll
        for (int hh = 0; hh < 2; ++hh) {
            float mx = -1e30f;
            #pragma unroll
            for (int ni = 0; ni < 8; ++ni)
                mx = fmaxf(mx, fmaxf(S[ni][2*hh], S[ni][2*hh+1]));
            mx = fmaxf(mx, __shfl_xor_sync(0xffffffffu, mx, 1));
            mx = fmaxf(mx, __shfl_xor_sync(0xffffffffu, mx, 2));
            float nm = fmaxf(mrow[hh], mx);
            float corr = __expf(mrow[hh] - nm);
            mrow[hh] = nm;
            float rs = 0.f;
            #pragma unroll
            for (int ni = 0; ni < 8; ++ni) {
                float p0 = __expf(S[ni][2*hh]   - nm);
                float p1 = __expf(S[ni][2*hh+1] - nm);
                S[ni][2*hh] = p0; S[ni][2*hh+1] = p1;
                rs += p0 + p1;
            }
            rs += __shfl_xor_sync(0xffffffffu, rs, 1);
            rs += __shfl_xor_sync(0xffffffffu, rs, 2);
            lrow[hh] = lrow[hh] * corr + rs;
            #pragma unroll
            for (int ni = 0; ni < 8; ++ni) {
                O[ni][2*hh]   *= corr;
                O[ni][2*hh+1] *= corr;
            }
        }

        // store P (tf32) into warp-private rows of sP
        __syncwarp();
        {
            int row = w * 16 + lr;
            #pragma unroll
            for (int ni = 0; ni < 8; ++ni) {
                int col = ni * 8 + 2 * lc;
                *(float2*)&sP[row * KPAD + col] =
                    make_float2(tf32r(S[ni][0]), tf32r(S[ni][1]));
                *(float2*)&sP[(row + 8) * KPAD + col] =
                    make_float2(tf32r(S[ni][2]), tf32r(S[ni][3]));
            }
        }
        __syncwarp();

        // O += P @ V
        #pragma unroll
        for (int ks = 0; ks < 8; ++ks) {
            float af[4];
            int row = w * 16 + lr;
            af[0] = sP[row * KPAD + ks * 8 + lc];
            af[1] = sP[(row + 8) * KPAD + ks * 8 + lc];
            af[2] = sP[row * KPAD + ks * 8 + 4 + lc];
            af[3] = sP[(row + 8) * KPAD + ks * 8 + 4 + lc];
            #pragma unroll
            for (int ni = 0; ni < 8; ++ni) {
                float bf[2];
                bf[0] = sV[(ks * 8 + lc) * VPAD + ni * 8 + lr];
                bf[1] = sV[(ks * 8 + lc + 4) * VPAD + ni * 8 + lr];
                mma8(O[ni], af, bf);
            }
        }
    }

    // normalized output, [L,B,D] layout, fp16
    #pragma unroll
    for (int hh = 0; hh < 2; ++hh) {
        int r = w * 16 + lr + hh * 8;
        int l = bq * QROWS + r;
        float inv = 1.0f / lrow[hh];
        __half* po = out + (size_t)(l * BATCH + b) * DMODEL + h * HD;
        #pragma unroll
        for (int ni = 0; ni < 8; ++ni)
            *(__half2*)&po[ni * 8 + 2 * lc] =
                __floats2half2_rn(O[ni][2*hh] * inv, O[ni][2*hh+1] * inv);
    }
}

// ---------------- launcher --------------------------------------------------
extern "C" void kernel_launch(void* const* d_in, const int* in_sizes, int n_in,
                              void* d_out, int out_size)
{
    const float* x      = (const float*)d_in[0];
    const float* ln1_g  = (const float*)d_in[1];
    const float* ln1_b  = (const float*)d_in[2];
    const float* w_attn = (const float*)d_in[3];
    const float* b_attn = (const float*)d_in[4];
    const float* w_proj = (const float*)d_in[5];
    const float* b_proj = (const float*)d_in[6];
    const float* ln2_g  = (const float*)d_in[7];
    const float* ln2_b  = (const float*)d_in[8];
    const float* w_fc   = (const float*)d_in[9];
    const float* b_fc   = (const float*)d_in[10];
    const float* w_out  = (const float*)d_in[11];
    const float* b_out  = (const float*)d_in[12];

    float* out     = (float*)d_out;
    float* present = out + (size_t)SEQ * BATCH * DMODEL;

    __half *h16, *attn16, *h2_16, *m16, *wt_attn, *wt_proj, *wt_fc, *wt_out;
    float *qkvp, *x1;
    cudaGetSymbolAddress((void**)&h16,     g_h16);
    cudaGetSymbolAddress((void**)&qkvp,    g_qkv);
    cudaGetSymbolAddress((void**)&attn16,  g_attn16);
    cudaGetSymbolAddress((void**)&x1,      g_x1);
    cudaGetSymbolAddress((void**)&h2_16,   g_h2_16);
    cudaGetSymbolAddress((void**)&m16,     g_m16);
    cudaGetSymbolAddress((void**)&wt_attn, g_wt_attn);
    cudaGetSymbolAddress((void**)&wt_proj, g_wt_proj);
    cudaGetSymbolAddress((void**)&wt_fc,   g_wt_fc);
    cudaGetSymbolAddress((void**)&wt_out,  g_wt_out);

    cudaFuncSetAttribute(attn_kernel, cudaFuncAttributeMaxDynamicSharedMemorySize, ATTN_SMEM);
    cudaFuncSetAttribute(hgemm<0>, cudaFuncAttributeMaxDynamicSharedMemorySize, GEMM_SMEM);
    cudaFuncSetAttribute(hgemm<1>, cudaFuncAttributeMaxDynamicSharedMemorySize, GEMM_SMEM);
    cudaFuncSetAttribute(hgemm<2>, cudaFuncAttributeMaxDynamicSharedMemorySize, GEMM_SMEM);

    dim3 tb(32, 8);
    // 0. weight transpose+convert to fp16 [N,K]
    transpose_w<<<dim3(3*DMODEL/32, DMODEL/32), tb>>>(w_attn, wt_attn, DMODEL, 3*DMODEL);
    transpose_w<<<dim3(DMODEL/32,   DMODEL/32), tb>>>(w_proj, wt_proj, DMODEL, DMODEL);
    transpose_w<<<dim3(DFF/32,      DMODEL/32), tb>>>(w_fc,   wt_fc,   DMODEL, DFF);
    transpose_w<<<dim3(DMODEL/32,   DFF/32),    tb>>>(w_out,  wt_out,  DFF,    DMODEL);

    // 1. h = LN1(x) -> fp16
    ln_kernel<<<ROWS, 256>>>(x, ln1_g, ln1_b, h16);
    // 2. qkv = h @ w_attn + b_attn  (fp32 out)
    hgemm<0><<<dim3(3*DMODEL/128, ROWS/128), 256, GEMM_SMEM>>>(
        h16, wt_attn, b_attn, nullptr, qkvp, nullptr, ROWS, 3*DMODEL, DMODEL);
    // 3. present (k, v) into d_out
    kvcopy_kernel<<<(2 * BATCH * NH * SEQ * 16) / 256, 256>>>(qkvp, present);
    // 4. attention -> attn16  [L,B,D] fp16
    attn_kernel<<<dim3(SEQ / QROWS, NH, BATCH), 256, ATTN_SMEM>>>(qkvp, present, attn16);
    // 5. x1 = x + attn @ w_proj + b_proj (fp32 out)
    hgemm<1><<<dim3(DMODEL/128, ROWS/128), 256, GEMM_SMEM>>>(
        attn16, wt_proj, b_proj, x, x1, nullptr, ROWS, DMODEL, DMODEL);
    // 6. h2 = LN2(x1) -> fp16
    ln_kernel<<<ROWS, 256>>>(x1, ln2_g, ln2_b, h2_16);
    // 7. m = gelu(h2 @ w_fc + b_fc) -> fp16
    hgemm<2><<<dim3(DFF/128, ROWS/128), 256, GEMM_SMEM>>>(
        h2_16, wt_fc, b_fc, nullptr, nullptr, m16, ROWS, DFF, DMODEL);
    // 8. out_x = x1 + m @ w_out + b_out (fp32 out)
    hgemm<1><<<dim3(DMODEL/128, ROWS/128), 256, GEMM_SMEM>>>(
        m16, wt_out, b_out, x1, out, nullptr, ROWS, DMODEL, DFF);
}

// round 9
// speedup vs baseline: 5.5700x; 1.3703x over previous
#include <cuda_runtime.h>
#include <cuda_fp16.h>
#include <math.h>
#include <stdint.h>

#define SEQ    2048
#define BATCH  2
#define DMODEL 1024
#define NH     16
#define HD     64
#define DFF    4096
#define ROWS   (SEQ*BATCH)   // 4096

// ---------------- scratch (device globals; no allocation allowed) ----------
__device__ __half g_h16  [ROWS*DMODEL];      // LN1 out (fp16)
__device__ __half g_q16  [ROWS*DMODEL];      // Q (fp16, pre-scaled by 1/8)
__device__ __half g_kv16 [2*BATCH*NH*SEQ*HD];// K,V fp16 copy [2,B,H,L,hd]
__device__ __half g_attn16[ROWS*DMODEL];     // attention out (fp16)
__device__ float  g_x1   [ROWS*DMODEL];      // x + attn_proj (fp32)
__device__ __half g_h2_16[ROWS*DMODEL];      // LN2 out (fp16)
__device__ __half g_m16  [ROWS*DFF];         // gelu(fc) out (fp16)
// transposed fp16 weights [N,K]
__device__ __half g_wt_attn[3*DMODEL*DMODEL];
__device__ __half g_wt_proj[DMODEL*DMODEL];
__device__ __half g_wt_fc  [DFF*DMODEL];
__device__ __half g_wt_out [DMODEL*DFF];

// ---------------- helpers ----------------------------------------------------
__device__ __forceinline__ uint32_t smem_u32(const void* p)
{
    return (uint32_t)__cvta_generic_to_shared(p);
}

__device__ __forceinline__ void cp16(uint32_t dst, const void* src)
{
    asm volatile("cp.async.cg.shared.global [%0], [%1], 16;" :: "r"(dst), "l"(src) : "memory");
}

__device__ __forceinline__ void ldsm_x4(uint32_t* r, uint32_t addr)
{
    asm volatile("ldmatrix.sync.aligned.m8n8.x4.shared.b16 {%0,%1,%2,%3}, [%4];"
                 : "=r"(r[0]), "=r"(r[1]), "=r"(r[2]), "=r"(r[3]) : "r"(addr));
}

__device__ __forceinline__ void ldsm_x2(uint32_t* r, uint32_t addr)
{
    asm volatile("ldmatrix.sync.aligned.m8n8.x2.shared.b16 {%0,%1}, [%2];"
                 : "=r"(r[0]), "=r"(r[1]) : "r"(addr));
}

__device__ __forceinline__ void ldsm_x2t(uint32_t* r, uint32_t addr)
{
    asm volatile("ldmatrix.sync.aligned.m8n8.x2.trans.shared.b16 {%0,%1}, [%2];"
                 : "=r"(r[0]), "=r"(r[1]) : "r"(addr));
}

__device__ __forceinline__ void mma16816(float* c, const uint32_t* a, const uint32_t* b)
{
    asm volatile(
        "mma.sync.aligned.m16n8k16.row.col.f32.f16.f16.f32 "
        "{%0,%1,%2,%3}, {%4,%5,%6,%7}, {%8,%9}, {%0,%1,%2,%3};\n"
        : "+f"(c[0]), "+f"(c[1]), "+f"(c[2]), "+f"(c[3])
        : "r"(a[0]), "r"(a[1]), "r"(a[2]), "r"(a[3]),
          "r"(b[0]), "r"(b[1]));
}

__device__ __forceinline__ uint32_t pack_h2(float a, float b)
{
    __half2 h = __floats2half2_rn(a, b);
    return *reinterpret_cast<uint32_t*>(&h);
}

__device__ __forceinline__ float gelu_f(float v)
{
    float c = v + 0.044715f * v * v * v;
    return 0.5f * v * (1.0f + tanhf(0.7978845608028654f * c));
}

// ---------------- weight transpose+convert: W[K,N] f32 -> Wt[N,K] f16 ------
__global__ void transpose_w(const float* __restrict__ W, __half* __restrict__ Wt,
                            int K, int N)
{
    __shared__ float t[32][33];
    int n0 = blockIdx.x * 32, k0 = blockIdx.y * 32;
    int tx = threadIdx.x, ty = threadIdx.y;
    #pragma unroll
    for (int d = 0; d < 32; d += 8)
        t[ty + d][tx] = W[(size_t)(k0 + ty + d) * N + n0 + tx];
    __syncthreads();
    #pragma unroll
    for (int d = 0; d < 32; d += 8)
        Wt[(size_t)(n0 + ty + d) * K + k0 + tx] = __float2half_rn(t[tx][ty + d]);
}

// ---------------- LayerNorm: one CTA per row, fp16 output ------------------
__global__ void ln_kernel(const float* __restrict__ x,
                          const float* __restrict__ g,
                          const float* __restrict__ b,
                          __half* __restrict__ y)
{
    int row = blockIdx.x;
    int tid = threadIdx.x;
    const float4* xr = reinterpret_cast<const float4*>(x + (size_t)row * DMODEL);
    float4 v = xr[tid];

    __shared__ float red[8];
    __shared__ float stat[2];

    float s = v.x + v.y + v.z + v.w;
    #pragma unroll
    for (int o = 16; o; o >>= 1) s += __shfl_xor_sync(0xffffffffu, s, o);
    if ((tid & 31) == 0) red[tid >> 5] = s;
    __syncthreads();
    if (tid == 0) {
        float t = 0.f;
        #pragma unroll
        for (int i = 0; i < 8; i++) t += red[i];
        stat[0] = t * (1.0f / DMODEL);
    }
    __syncthreads();
    float mu = stat[0];

    float dx = v.x - mu, dy = v.y - mu, dz = v.z - mu, dw = v.w - mu;
    float s2 = dx*dx + dy*dy + dz*dz + dw*dw;
    #pragma unroll
    for (int o = 16; o; o >>= 1) s2 += __shfl_xor_sync(0xffffffffu, s2, o);
    if ((tid & 31) == 0) red[tid >> 5] = s2;
    __syncthreads();
    if (tid == 0) {
        float t = 0.f;
        #pragma unroll
        for (int i = 0; i < 8; i++) t += red[i];
        stat[1] = rsqrtf(t * (1.0f / DMODEL) + 1e-5f);
    }
    __syncthreads();
    float rstd = stat[1];

    const float4* gr = reinterpret_cast<const float4*>(g);
    const float4* br = reinterpret_cast<const float4*>(b);
    float4 gv = gr[tid], bv = br[tid];
    __half2 p0 = __floats2half2_rn(dx * rstd * gv.x + bv.x, dy * rstd * gv.y + bv.y);
    __half2 p1 = __floats2half2_rn(dz * rstd * gv.z + bv.z, dw * rstd * gv.w + bv.w);
    __half2* yr = reinterpret_cast<__half2*>(y + (size_t)row * DMODEL);
    yr[tid * 2 + 0] = p0;
    yr[tid * 2 + 1] = p1;
}

// ---------------- fp16 mma.sync GEMM ----------------------------------------
// C[M,N] = A[M,K]f16 @ Bt[N,K]f16^T + epilogue, fp32 accum.
// 128x128 tile, BK=32 halves, 4-stage cp.async ring, ldmatrix fragments.
// EPI: 0 = +bias (f32 out), 1 = +bias+res (f32 out), 2 = gelu(+bias) (f16 out)
// EPI 3 = qkv split: Q -> Ch (fp16, x0.125), K/V -> Cf (present fp32) + kvh (fp16)
#define BK        32
#define KROW      40                        // BK + 8 pad (halves); 80B stride
#define A_STAGE_H (128*KROW)                // halves
#define STAGE_B   (2*A_STAGE_H*2)           // A + B bytes = 20480
#define GSTAGES   4
#define GEMM_SMEM (GSTAGES*STAGE_B)         // 81920

template<int EPI>
__global__ void __launch_bounds__(256, 1)
hgemm(const __half* __restrict__ A, const __half* __restrict__ Bt,
      const float* __restrict__ bias, const float* __restrict__ res,
      float* __restrict__ Cf, __half* __restrict__ Ch,
      __half* __restrict__ kvh,
      int M, int N, int K)
{
    extern __shared__ char smem_raw[];
    uint32_t sbase = smem_u32(smem_raw);

    int tid = threadIdx.x;
    int w = tid >> 5, lane = tid & 31;
    int lr = lane >> 2, lc = lane & 3;
    int wm = w >> 2, wn = w & 3;
    int row0 = blockIdx.y * 128, col0 = blockIdx.x * 128;
    int KT = K / BK;

    float acc[4][4][4];
    #pragma unroll
    for (int i = 0; i < 4; ++i)
        #pragma unroll
        for (int j = 0; j < 4; ++j)
            acc[i][j][0] = acc[i][j][1] = acc[i][j][2] = acc[i][j][3] = 0.f;

    int r0 = tid >> 2, s0 = (tid & 3);
    int r1 = (tid + 256) >> 2, s1 = (tid & 3);
    const char* Asrc0 = (const char*)(A + (size_t)(row0 + r0) * K + s0 * 8);
    const char* Asrc1 = (const char*)(A + (size_t)(row0 + r1) * K + s1 * 8);
    const char* Bsrc0 = (const char*)(Bt + (size_t)(col0 + r0) * K + s0 * 8);
    const char* Bsrc1 = (const char*)(Bt + (size_t)(col0 + r1) * K + s1 * 8);
    uint32_t dA0 = (uint32_t)(r0 * KROW + s0 * 8) * 2;
    uint32_t dA1 = (uint32_t)(r1 * KROW + s1 * 8) * 2;

    uint32_t aFrag[2], bFrag[2];
    #pragma unroll
    for (int kk = 0; kk < 2; ++kk) {
        aFrag[kk] = (uint32_t)((wm * 64 + (lane & 15)) * KROW + kk * 16 + (lane >> 4) * 8) * 2;
        bFrag[kk] = (uint32_t)(A_STAGE_H * 2) +
                    (uint32_t)((wn * 32 + (lane & 7)) * KROW + kk * 16 + ((lane >> 3) & 1) * 8) * 2;
    }

    auto load_stage = [&](int slot, int kc) {
        uint32_t ab = sbase + slot * STAGE_B;
        uint32_t bb = ab + A_STAGE_H * 2;
        size_t koff = (size_t)kc * BK * 2;
        cp16(ab + dA0, Asrc0 + koff);
        cp16(ab + dA1, Asrc1 + koff);
        cp16(bb + dA0, Bsrc0 + koff);
        cp16(bb + dA1, Bsrc1 + koff);
    };

    #pragma unroll
    for (int c = 0; c < GSTAGES - 1; ++c) {
        load_stage(c, c);
        asm volatile("cp.async.commit_group;" ::: "memory");
    }

    for (int i = 0; i < KT; ++i) {
        asm volatile("cp.async.wait_group %0;" :: "n"(GSTAGES - 2) : "memory");
        __syncthreads();

        if (i + GSTAGES - 1 < KT)
            load_stage((i + GSTAGES - 1) & (GSTAGES - 1), i + GSTAGES - 1);
        asm volatile("cp.async.commit_group;" ::: "memory");

        uint32_t stg = sbase + (i & (GSTAGES - 1)) * STAGE_B;
        #pragma unroll
        for (int kk = 0; kk < 2; ++kk) {
            uint32_t af[4][4], bf[4][2];
            #pragma unroll
            for (int mi = 0; mi < 4; ++mi)
                ldsm_x4(af[mi], stg + aFrag[kk] + (uint32_t)(mi * 16 * KROW) * 2);
            #pragma unroll
            for (int ni = 0; ni < 4; ++ni)
                ldsm_x2(bf[ni], stg + bFrag[kk] + (uint32_t)(ni * 8 * KROW) * 2);
            #pragma unroll
            for (int mi = 0; mi < 4; ++mi)
                #pragma unroll
                for (int ni = 0; ni < 4; ++ni)
                    mma16816(acc[mi][ni], af[mi], bf[ni]);
        }
        __syncthreads();
    }

    int sect = col0 >> 10;   // used by EPI==3

    #pragma unroll
    for (int mi = 0; mi < 4; ++mi) {
        #pragma unroll
        for (int hh = 0; hh < 2; ++hh) {
            int r = row0 + wm * 64 + mi * 16 + lr + hh * 8;
            #pragma unroll
            for (int ni = 0; ni < 4; ++ni) {
                int c = col0 + wn * 32 + ni * 8 + 2 * lc;
                float2 bv = *(const float2*)&bias[c];
                float ox = acc[mi][ni][2 * hh + 0] + bv.x;
                float oy = acc[mi][ni][2 * hh + 1] + bv.y;
                if (EPI == 1) {
                    float2 rv = *(const float2*)&res[(size_t)r * N + c];
                    ox += rv.x; oy += rv.y;
                }
                if (EPI == 2) {
                    *(__half2*)&Ch[(size_t)r * N + c] =
                        __floats2half2_rn(gelu_f(ox), gelu_f(oy));
                } else if (EPI == 3) {
                    if (sect == 0) {
                        // Q: fp16, pre-scaled by 1/sqrt(HD)=0.125
                        *(__half2*)&Ch[(size_t)r * DMODEL + c] =
                            __floats2half2_rn(ox * 0.125f, oy * 0.125f);
                    } else {
                        int d  = c & (DMODEL - 1);
                        int hh2 = d >> 6, hd = d & (HD - 1);
                        int l = r >> 1, bb = r & 1;
                        size_t pidx = ((((size_t)(sect - 1) * BATCH + bb) * NH + hh2) * SEQ + l) * HD + hd;
                        *(float2*)&Cf[pidx] = make_float2(ox, oy);
                        *(__half2*)&kvh[pidx] = __floats2half2_rn(ox, oy);
                    }
                } else {
                    *(float2*)&Cf[(size_t)r * N + c] = make_float2(ox, oy);
                }
            }
        }
    }
}

// ---------------- Flash attention (fp16 mma.m16n8k16, register P) ----------
// CTA: 128 queries x (head, batch), 256 threads = 8 warps; warp w owns query
// rows 16w..16w+15. K/V fp16 staged via cp.async double buffer.
#define AQP   72                         // row pitch (halves) = 144B
#define KVBUF (64*AQP)                   // halves per K (or V) tile
#define ATTN_SMEM ((128*AQP + 2*2*KVBUF) * 2)
#define NKB   (SEQ/64)

__global__ void __launch_bounds__(256)
attn_kernel(const __half* __restrict__ q16, const __half* __restrict__ kv16,
            __half* __restrict__ out)
{
    extern __shared__ __half sh[];
    __half* sQ  = sh;                    // 128 x AQP
    __half* sKV = sh + 128 * AQP;        // 2 buffers x (K 64xAQP, V 64xAQP)

    int tid  = threadIdx.x;
    int w = tid >> 5, lane = tid & 31;
    int lr = lane >> 2, lc = lane & 3;
    int bq = blockIdx.x, h = blockIdx.y, b = blockIdx.z;

    const __half* Kg = kv16 + ((size_t)b * NH + h) * SEQ * HD;
    const __half* Vg = kv16 + (((size_t)BATCH + b) * NH + h) * SEQ * HD;

    // Q loads (own cp.async group)
    #pragma unroll
    for (int i = 0; i < 4; ++i) {
        int ck = i * 256 + tid;
        int r = ck >> 3, seg = ck & 7;
        cp16(smem_u32(sQ + r * AQP + seg * 8),
             q16 + (((size_t)(bq * 128 + r) * BATCH + b) * DMODEL + h * HD + seg * 8));
    }
    asm volatile("cp.async.commit_group;" ::: "memory");

    auto load_kv = [&](int kb, int buf) {
        __half* Kb = sKV + buf * 2 * KVBUF;
        __half* Vb = Kb + KVBUF;
        #pragma unroll
        for (int i = 0; i < 2; ++i) {
            int ck = i * 256 + tid;
            int r = ck >> 3, seg = ck & 7;
            cp16(smem_u32(Kb + r * AQP + seg * 8),
                 Kg + (size_t)(kb * 64 + r) * HD + seg * 8);
            cp16(smem_u32(Vb + r * AQP + seg * 8),
                 Vg + (size_t)(kb * 64 + r) * HD + seg * 8);
        }
    };

    load_kv(0, 0);
    asm volatile("cp.async.commit_group;" ::: "memory");

    // preload Q fragments (after Q group done: allow 1 pending = KV0)
    asm volatile("cp.async.wait_group 1;" ::: "memory");
    __syncthreads();
    uint32_t qa[4][4];
    #pragma unroll
    for (int kk = 0; kk < 4; ++kk)
        ldsm_x4(qa[kk], smem_u32(sQ + ((w * 16 + (lane & 15)) * AQP
                                       + kk * 16 + (lane >> 4) * 8)));

    float mrow[2] = {-1e30f, -1e30f};
    float lrow[2] = {0.f, 0.f};
    float O[8][4];
    #pragma unroll
    for (int ni = 0; ni < 8; ++ni)
        O[ni][0] = O[ni][1] = O[ni][2] = O[ni][3] = 0.f;

    for (int kb = 0; kb < NKB; ++kb) {
        if (kb + 1 < NKB) load_kv(kb + 1, (kb + 1) & 1);
        asm volatile("cp.async.commit_group;" ::: "memory");
        asm volatile("cp.async.wait_group 1;" ::: "memory");
        __syncthreads();

        uint32_t Kb = smem_u32(sKV + (kb & 1) * 2 * KVBUF);
        uint32_t Vb = Kb + KVBUF * 2;

        // S = Q @ K^T : warp computes 16 x 64
        float S[8][4];
        #pragma unroll
        for (int ni = 0; ni < 8; ++ni)
            S[ni][0] = S[ni][1] = S[ni][2] = S[ni][3] = 0.f;
        #pragma unroll
        for (int kk = 0; kk < 4; ++kk) {
            #pragma unroll
            for (int ni = 0; ni < 8; ++ni) {
                uint32_t kf[2];
                ldsm_x2(kf, Kb + ((ni * 8 + (lane & 7)) * AQP
                                  + kk * 16 + ((lane >> 3) & 1) * 8) * 2);
                mma16816(S[ni], qa[kk], kf);
            }
        }

        // online softmax (rows lr / lr+8; quad lanes hold 2 cols each)
        #pragma unroll
        for (int hh = 0; hh < 2; ++hh) {
            float mx = -1e30f;
            #pragma unroll
            for (int ni = 0; ni < 8; ++ni)
                mx = fmaxf(mx, fmaxf(S[ni][2*hh], S[ni][2*hh+1]));
            mx = fmaxf(mx, __shfl_xor_sync(0xffffffffu, mx, 1));
            mx = fmaxf(mx, __shfl_xor_sync(0xffffffffu, mx, 2));
            float nm = fmaxf(mrow[hh], mx);
            float corr = __expf(mrow[hh] - nm);
            mrow[hh] = nm;
            float rs = 0.f;
            #pragma unroll
            for (int ni = 0; ni < 8; ++ni) {
                float p0 = __expf(S[ni][2*hh]   - nm);
                float p1 = __expf(S[ni][2*hh+1] - nm);
                S[ni][2*hh] = p0; S[ni][2*hh+1] = p1;
                rs += p0 + p1;
            }
            rs += __shfl_xor_sync(0xffffffffu, rs, 1);
            rs += __shfl_xor_sync(0xffffffffu, rs, 2);
            lrow[hh] = lrow[hh] * corr + rs;
            #pragma unroll
            for (int ni = 0; ni < 8; ++ni) {
                O[ni][2*hh]   *= corr;
                O[ni][2*hh+1] *= corr;
            }
        }

        // O += P @ V  (P converted to fp16 in registers; V via ldmatrix.trans)
        #pragma unroll
        for (int kk = 0; kk < 4; ++kk) {
            uint32_t pa[4];
            pa[0] = pack_h2(S[2*kk][0],   S[2*kk][1]);
            pa[1] = pack_h2(S[2*kk][2],   S[2*kk][3]);
            pa[2] = pack_h2(S[2*kk+1][0], S[2*kk+1][1]);
            pa[3] = pack_h2(S[2*kk+1][2], S[2*kk+1][3]);
            #pragma unroll
            for (int ni = 0; ni < 8; ++ni) {
                uint32_t vf[2];
                ldsm_x2t(vf, Vb + ((kk * 16 + ((lane >> 3) & 1) * 8 + (lane & 7)) * AQP
                                   + ni * 8) * 2);
                mma16816(O[ni], pa, vf);
            }
        }
        __syncthreads();
    }

    // normalized output, [L,B,D] layout, fp16
    #pragma unroll
    for (int hh = 0; hh < 2; ++hh) {
        int r = w * 16 + lr + hh * 8;
        int l = bq * 128 + r;
        float inv = 1.0f / lrow[hh];
        __half* po = out + (size_t)(l * BATCH + b) * DMODEL + h * HD;
        #pragma unroll
        for (int ni = 0; ni < 8; ++ni)
            *(__half2*)&po[ni * 8 + 2 * lc] =
                __floats2half2_rn(O[ni][2*hh] * inv, O[ni][2*hh+1] * inv);
    }
}

// ---------------- launcher --------------------------------------------------
extern "C" void kernel_launch(void* const* d_in, const int* in_sizes, int n_in,
                              void* d_out, int out_size)
{
    const float* x      = (const float*)d_in[0];
    const float* ln1_g  = (const float*)d_in[1];
    const float* ln1_b  = (const float*)d_in[2];
    const float* w_attn = (const float*)d_in[3];
    const float* b_attn = (const float*)d_in[4];
    const float* w_proj = (const float*)d_in[5];
    const float* b_proj = (const float*)d_in[6];
    const float* ln2_g  = (const float*)d_in[7];
    const float* ln2_b  = (const float*)d_in[8];
    const float* w_fc   = (const float*)d_in[9];
    const float* b_fc   = (const float*)d_in[10];
    const float* w_out  = (const float*)d_in[11];
    const float* b_out  = (const float*)d_in[12];

    float* out     = (float*)d_out;
    float* present = out + (size_t)SEQ * BATCH * DMODEL;

    __half *h16, *q16, *kv16, *attn16, *h2_16, *m16;
    __half *wt_attn, *wt_proj, *wt_fc, *wt_out;
    float *x1;
    cudaGetSymbolAddress((void**)&h16,     g_h16);
    cudaGetSymbolAddress((void**)&q16,     g_q16);
    cudaGetSymbolAddress((void**)&kv16,    g_kv16);
    cudaGetSymbolAddress((void**)&attn16,  g_attn16);
    cudaGetSymbolAddress((void**)&x1,      g_x1);
    cudaGetSymbolAddress((void**)&h2_16,   g_h2_16);
    cudaGetSymbolAddress((void**)&m16,     g_m16);
    cudaGetSymbolAddress((void**)&wt_attn, g_wt_attn);
    cudaGetSymbolAddress((void**)&wt_proj, g_wt_proj);
    cudaGetSymbolAddress((void**)&wt_fc,   g_wt_fc);
    cudaGetSymbolAddress((void**)&wt_out,  g_wt_out);

    cudaFuncSetAttribute(attn_kernel, cudaFuncAttributeMaxDynamicSharedMemorySize, ATTN_SMEM);
    cudaFuncSetAttribute(hgemm<0>, cudaFuncAttributeMaxDynamicSharedMemorySize, GEMM_SMEM);
    cudaFuncSetAttribute(hgemm<1>, cudaFuncAttributeMaxDynamicSharedMemorySize, GEMM_SMEM);
    cudaFuncSetAttribute(hgemm<2>, cudaFuncAttributeMaxDynamicSharedMemorySize, GEMM_SMEM);
    cudaFuncSetAttribute(hgemm<3>, cudaFuncAttributeMaxDynamicSharedMemorySize, GEMM_SMEM);

    dim3 tb(32, 8);
    // 0. weight transpose+convert to fp16 [N,K]
    transpose_w<<<dim3(3*DMODEL/32, DMODEL/32), tb>>>(w_attn, wt_attn, DMODEL, 3*DMODEL);
    transpose_w<<<dim3(DMODEL/32,   DMODEL/32), tb>>>(w_proj, wt_proj, DMODEL, DMODEL);
    transpose_w<<<dim3(DFF/32,      DMODEL/32), tb>>>(w_fc,   wt_fc,   DMODEL, DFF);
    transpose_w<<<dim3(DMODEL/32,   DFF/32),    tb>>>(w_out,  wt_out,  DFF,    DMODEL);

    // 1. h = LN1(x) -> fp16
    ln_kernel<<<ROWS, 256>>>(x, ln1_g, ln1_b, h16);
    // 2. qkv GEMM, fused split epilogue:
    //    Q -> q16 (fp16, x0.125), K/V -> present (fp32) + kv16 (fp16)
    hgemm<3><<<dim3(3*DMODEL/128, ROWS/128), 256, GEMM_SMEM>>>(
        h16, wt_attn, b_attn, nullptr, present, q16, kv16, ROWS, 3*DMODEL, DMODEL);
    // 3. attention -> attn16  [L,B,D] fp16
    attn_kernel<<<dim3(SEQ / 128, NH, BATCH), 256, ATTN_SMEM>>>(q16, kv16, attn16);
    // 4. x1 = x + attn @ w_proj + b_proj (fp32 out)
    hgemm<1><<<dim3(DMODEL/128, ROWS/128), 256, GEMM_SMEM>>>(
        attn16, wt_proj, b_proj, x, x1, nullptr, nullptr, ROWS, DMODEL, DMODEL);
    // 5. h2 = LN2(x1) -> fp16
    ln_kernel<<<ROWS, 256>>>(x1, ln2_g, ln2_b, h2_16);
    // 6. m = gelu(h2 @ w_fc + b_fc) -> fp16
    hgemm<2><<<dim3(DFF/128, ROWS/128), 256, GEMM_SMEM>>>(
        h2_16, wt_fc, b_fc, nullptr, nullptr, m16, nullptr, ROWS, DFF, DMODEL);
    // 7. out_x = x1 + m @ w_out + b_out (fp32 out)
    hgemm<1><<<dim3(DMODEL/128, ROWS/128), 256, GEMM_SMEM>>>(
        m16, wt_out, b_out, x1, out, nullptr, nullptr, ROWS, DMODEL, DFF);
}

// round 10
// speedup vs baseline: 6.2760x; 1.1267x over previous
#include <cuda_runtime.h>
#include <cuda_fp16.h>
#include <math.h>
#include <stdint.h>

#define SEQ    2048
#define BATCH  2
#define DMODEL 1024
#define NH     16
#define HD     64
#define DFF    4096
#define ROWS   (SEQ*BATCH)   // 4096

// ---------------- scratch (device globals; no allocation allowed) ----------
__device__ __half g_h16  [ROWS*DMODEL];      // LN1 out (fp16)
__device__ __half g_q16  [ROWS*DMODEL];      // Q (fp16, pre-scaled by 1/8)
__device__ __half g_kv16 [2*BATCH*NH*SEQ*HD];// K,V fp16 copy [2,B,H,L,hd]
__device__ __half g_attn16[ROWS*DMODEL];     // attention out (fp16)
__device__ float  g_x1   [ROWS*DMODEL];      // x + attn_proj (fp32)
__device__ __half g_h2_16[ROWS*DMODEL];      // LN2 out (fp16)
__device__ __half g_m16  [ROWS*DFF];         // gelu(fc) out (fp16)
// transposed fp16 weights [N,K]
__device__ __half g_wt_attn[3*DMODEL*DMODEL];
__device__ __half g_wt_proj[DMODEL*DMODEL];
__device__ __half g_wt_fc  [DFF*DMODEL];
__device__ __half g_wt_out [DMODEL*DFF];

// ---------------- helpers ----------------------------------------------------
__device__ __forceinline__ uint32_t smem_u32(const void* p)
{
    return (uint32_t)__cvta_generic_to_shared(p);
}

__device__ __forceinline__ void cp16(uint32_t dst, const void* src)
{
    asm volatile("cp.async.cg.shared.global [%0], [%1], 16;" :: "r"(dst), "l"(src) : "memory");
}

__device__ __forceinline__ void ldsm_x4(uint32_t* r, uint32_t addr)
{
    asm volatile("ldmatrix.sync.aligned.m8n8.x4.shared.b16 {%0,%1,%2,%3}, [%4];"
                 : "=r"(r[0]), "=r"(r[1]), "=r"(r[2]), "=r"(r[3]) : "r"(addr));
}

__device__ __forceinline__ void ldsm_x2(uint32_t* r, uint32_t addr)
{
    asm volatile("ldmatrix.sync.aligned.m8n8.x2.shared.b16 {%0,%1}, [%2];"
                 : "=r"(r[0]), "=r"(r[1]) : "r"(addr));
}

__device__ __forceinline__ void ldsm_x2t(uint32_t* r, uint32_t addr)
{
    asm volatile("ldmatrix.sync.aligned.m8n8.x2.trans.shared.b16 {%0,%1}, [%2];"
                 : "=r"(r[0]), "=r"(r[1]) : "r"(addr));
}

__device__ __forceinline__ void mma16816(float* c, const uint32_t* a, const uint32_t* b)
{
    asm volatile(
        "mma.sync.aligned.m16n8k16.row.col.f32.f16.f16.f32 "
        "{%0,%1,%2,%3}, {%4,%5,%6,%7}, {%8,%9}, {%0,%1,%2,%3};\n"
        : "+f"(c[0]), "+f"(c[1]), "+f"(c[2]), "+f"(c[3])
        : "r"(a[0]), "r"(a[1]), "r"(a[2]), "r"(a[3]),
          "r"(b[0]), "r"(b[1]));
}

__device__ __forceinline__ uint32_t pack_h2(float a, float b)
{
    __half2 h = __floats2half2_rn(a, b);
    return *reinterpret_cast<uint32_t*>(&h);
}

__device__ __forceinline__ float gelu_f(float v)
{
    float c = v + 0.044715f * v * v * v;
    return 0.5f * v * (1.0f + tanhf(0.7978845608028654f * c));
}

// ---------------- weight transpose+convert: W[K,N] f32 -> Wt[N,K] f16 ------
__global__ void transpose_w(const float* __restrict__ W, __half* __restrict__ Wt,
                            int K, int N)
{
    __shared__ float t[32][33];
    int n0 = blockIdx.x * 32, k0 = blockIdx.y * 32;
    int tx = threadIdx.x, ty = threadIdx.y;
    #pragma unroll
    for (int d = 0; d < 32; d += 8)
        t[ty + d][tx] = W[(size_t)(k0 + ty + d) * N + n0 + tx];
    __syncthreads();
    #pragma unroll
    for (int d = 0; d < 32; d += 8)
        Wt[(size_t)(n0 + ty + d) * K + k0 + tx] = __float2half_rn(t[tx][ty + d]);
}

// ---------------- LayerNorm: one CTA per row, fp16 output ------------------
__global__ void ln_kernel(const float* __restrict__ x,
                          const float* __restrict__ g,
                          const float* __restrict__ b,
                          __half* __restrict__ y)
{
    int row = blockIdx.x;
    int tid = threadIdx.x;
    const float4* xr = reinterpret_cast<const float4*>(x + (size_t)row * DMODEL);
    float4 v = xr[tid];

    __shared__ float red[8];
    __shared__ float stat[2];

    float s = v.x + v.y + v.z + v.w;
    #pragma unroll
    for (int o = 16; o; o >>= 1) s += __shfl_xor_sync(0xffffffffu, s, o);
    if ((tid & 31) == 0) red[tid >> 5] = s;
    __syncthreads();
    if (tid == 0) {
        float t = 0.f;
        #pragma unroll
        for (int i = 0; i < 8; i++) t += red[i];
        stat[0] = t * (1.0f / DMODEL);
    }
    __syncthreads();
    float mu = stat[0];

    float dx = v.x - mu, dy = v.y - mu, dz = v.z - mu, dw = v.w - mu;
    float s2 = dx*dx + dy*dy + dz*dz + dw*dw;
    #pragma unroll
    for (int o = 16; o; o >>= 1) s2 += __shfl_xor_sync(0xffffffffu, s2, o);
    if ((tid & 31) == 0) red[tid >> 5] = s2;
    __syncthreads();
    if (tid == 0) {
        float t = 0.f;
        #pragma unroll
        for (int i = 0; i < 8; i++) t += red[i];
        stat[1] = rsqrtf(t * (1.0f / DMODEL) + 1e-5f);
    }
    __syncthreads();
    float rstd = stat[1];

    const float4* gr = reinterpret_cast<const float4*>(g);
    const float4* br = reinterpret_cast<const float4*>(b);
    float4 gv = gr[tid], bv = br[tid];
    __half2 p0 = __floats2half2_rn(dx * rstd * gv.x + bv.x, dy * rstd * gv.y + bv.y);
    __half2 p1 = __floats2half2_rn(dz * rstd * gv.z + bv.z, dw * rstd * gv.w + bv.w);
    __half2* yr = reinterpret_cast<__half2*>(y + (size_t)row * DMODEL);
    yr[tid * 2 + 0] = p0;
    yr[tid * 2 + 1] = p1;
}

// ---------------- fp16 mma.sync GEMM ----------------------------------------
// C[M,N] = A[M,K]f16 @ Bt[N,K]f16^T + epilogue, fp32 accum.
// 128x256 CTA tile, BK=32 halves, 4-stage cp.async ring, ldmatrix x4 feeds.
// 256 threads = 8 warps (2x4); warp tile 64x64 = 4m x 8n of m16n8k16.
// EPI: 0 = +bias (f32 out), 1 = +bias+res (f32 out), 2 = gelu(+bias) (f16 out)
// EPI 3 = qkv split: Q -> Ch (fp16, x0.125), K/V -> Cf (present fp32) + kvh (fp16)
#define BK        32
#define KROW      40                        // BK + 8 pad (halves); 80B stride
#define A_STAGE_B (128*KROW*2)              // 10240 bytes
#define B_STAGE_B (256*KROW*2)              // 20480 bytes
#define STAGE_B   (A_STAGE_B + B_STAGE_B)   // 30720 bytes
#define GSTAGES   4
#define GEMM_SMEM (GSTAGES*STAGE_B)         // 122880

template<int EPI>
__global__ void __launch_bounds__(256, 1)
hgemm(const __half* __restrict__ A, const __half* __restrict__ Bt,
      const float* __restrict__ bias, const float* __restrict__ res,
      float* __restrict__ Cf, __half* __restrict__ Ch,
      __half* __restrict__ kvh,
      int M, int N, int K)
{
    extern __shared__ char smem_raw[];
    uint32_t sbase = smem_u32(smem_raw);

    int tid = threadIdx.x;
    int w = tid >> 5, lane = tid & 31;
    int lr = lane >> 2, lc = lane & 3;
    int wm = w >> 2, wn = w & 3;                 // 2 x 4 warp grid
    int row0 = blockIdx.y * 128, col0 = blockIdx.x * 256;
    int KT = K / BK;

    float acc[4][8][4];
    #pragma unroll
    for (int i = 0; i < 4; ++i)
        #pragma unroll
        for (int j = 0; j < 8; ++j)
            acc[i][j][0] = acc[i][j][1] = acc[i][j][2] = acc[i][j][3] = 0.f;

    // load mapping: 16B chunks; chunk c -> row c>>2, seg c&3.
    // A: 512 chunks (2/thread), B: 1024 chunks (4/thread).
    int ar = tid >> 2, seg = tid & 3;
    const char* Asrc0 = (const char*)(A + (size_t)(row0 + ar) * K + seg * 8);
    const char* Asrc1 = (const char*)(A + (size_t)(row0 + ar + 64) * K + seg * 8);
    const char* Bsrc0 = (const char*)(Bt + (size_t)(col0 + ar) * K + seg * 8);
    const char* Bsrc1 = (const char*)(Bt + (size_t)(col0 + ar + 64) * K + seg * 8);
    const char* Bsrc2 = (const char*)(Bt + (size_t)(col0 + ar + 128) * K + seg * 8);
    const char* Bsrc3 = (const char*)(Bt + (size_t)(col0 + ar + 192) * K + seg * 8);
    uint32_t dA0 = (uint32_t)(ar * KROW + seg * 8) * 2;
    uint32_t dA1 = dA0 + (uint32_t)(64 * KROW) * 2;
    uint32_t dB0 = dA0, dB1 = dA1;
    uint32_t dB2 = dA0 + (uint32_t)(128 * KROW) * 2;
    uint32_t dB3 = dA0 + (uint32_t)(192 * KROW) * 2;

    // fragment smem offsets (within a stage)
    int g = lane >> 3;   // 0..3
    uint32_t aFrag[2], bFrag[2];
    #pragma unroll
    for (int kk = 0; kk < 2; ++kk) {
        aFrag[kk] = (uint32_t)((wm * 64 + (lane & 15)) * KROW + kk * 16 + (lane >> 4) * 8) * 2;
        bFrag[kk] = (uint32_t)A_STAGE_B +
                    (uint32_t)((wn * 64 + (g >> 1) * 8 + (lane & 7)) * KROW
                               + kk * 16 + (g & 1) * 8) * 2;
    }

    auto load_stage = [&](int slot, int kc) {
        uint32_t ab = sbase + slot * STAGE_B;
        uint32_t bb = ab + A_STAGE_B;
        size_t koff = (size_t)kc * BK * 2;
        cp16(ab + dA0, Asrc0 + koff);
        cp16(ab + dA1, Asrc1 + koff);
        cp16(bb + dB0, Bsrc0 + koff);
        cp16(bb + dB1, Bsrc1 + koff);
        cp16(bb + dB2, Bsrc2 + koff);
        cp16(bb + dB3, Bsrc3 + koff);
    };

    #pragma unroll
    for (int c = 0; c < GSTAGES - 1; ++c) {
        load_stage(c, c);
        asm volatile("cp.async.commit_group;" ::: "memory");
    }

    for (int i = 0; i < KT; ++i) {
        asm volatile("cp.async.wait_group %0;" :: "n"(GSTAGES - 2) : "memory");
        __syncthreads();

        if (i + GSTAGES - 1 < KT)
            load_stage((i + GSTAGES - 1) & (GSTAGES - 1), i + GSTAGES - 1);
        asm volatile("cp.async.commit_group;" ::: "memory");

        uint32_t stg = sbase + (i & (GSTAGES - 1)) * STAGE_B;
        #pragma unroll
        for (int kk = 0; kk < 2; ++kk) {
            uint32_t af[4][4], bf[4][4];
            #pragma unroll
            for (int mi = 0; mi < 4; ++mi)
                ldsm_x4(af[mi], stg + aFrag[kk] + (uint32_t)(mi * 16 * KROW) * 2);
            #pragma unroll
            for (int np = 0; np < 4; ++np)
                ldsm_x4(bf[np], stg + bFrag[kk] + (uint32_t)(np * 16 * KROW) * 2);
            #pragma unroll
            for (int mi = 0; mi < 4; ++mi)
                #pragma unroll
                for (int np = 0; np < 4; ++np) {
                    mma16816(acc[mi][2*np],   af[mi], &bf[np][0]);
                    mma16816(acc[mi][2*np+1], af[mi], &bf[np][2]);
                }
        }
        __syncthreads();
    }

    int sect = col0 >> 10;   // used by EPI==3 (256 | 1024, so constant per tile)

    #pragma unroll
    for (int mi = 0; mi < 4; ++mi) {
        #pragma unroll
        for (int hh = 0; hh < 2; ++hh) {
            int r = row0 + wm * 64 + mi * 16 + lr + hh * 8;
            #pragma unroll
            for (int ni = 0; ni < 8; ++ni) {
                int c = col0 + wn * 64 + ni * 8 + 2 * lc;
                float2 bv = *(const float2*)&bias[c];
                float ox = acc[mi][ni][2 * hh + 0] + bv.x;
                float oy = acc[mi][ni][2 * hh + 1] + bv.y;
                if (EPI == 1) {
                    float2 rv = *(const float2*)&res[(size_t)r * N + c];
                    ox += rv.x; oy += rv.y;
                }
                if (EPI == 2) {
                    *(__half2*)&Ch[(size_t)r * N + c] =
                        __floats2half2_rn(gelu_f(ox), gelu_f(oy));
                } else if (EPI == 3) {
                    if (sect == 0) {
                        *(__half2*)&Ch[(size_t)r * DMODEL + c] =
                            __floats2half2_rn(ox * 0.125f, oy * 0.125f);
                    } else {
                        int d  = c & (DMODEL - 1);
                        int hh2 = d >> 6, hd = d & (HD - 1);
                        int l = r >> 1, bb = r & 1;
                        size_t pidx = ((((size_t)(sect - 1) * BATCH + bb) * NH + hh2) * SEQ + l) * HD + hd;
                        *(float2*)&Cf[pidx] = make_float2(ox, oy);
                        *(__half2*)&kvh[pidx] = __floats2half2_rn(ox, oy);
                    }
                } else {
                    *(float2*)&Cf[(size_t)r * N + c] = make_float2(ox, oy);
                }
            }
        }
    }
}

// ---------------- Flash attention (fp16 mma.m16n8k16, register P) ----------
// CTA: 128 queries x (head, batch), 256 threads = 8 warps; warp w owns query
// rows 16w..16w+15. K/V fp16 staged via cp.async double buffer.
#define AQP   72                         // row pitch (halves) = 144B
#define KVBUF (64*AQP)                   // halves per K (or V) tile
#define ATTN_SMEM ((128*AQP + 2*2*KVBUF) * 2)
#define NKB   (SEQ/64)

__global__ void __launch_bounds__(256)
attn_kernel(const __half* __restrict__ q16, const __half* __restrict__ kv16,
            __half* __restrict__ out)
{
    extern __shared__ __half sh[];
    __half* sQ  = sh;                    // 128 x AQP
    __half* sKV = sh + 128 * AQP;        // 2 buffers x (K 64xAQP, V 64xAQP)

    int tid  = threadIdx.x;
    int w = tid >> 5, lane = tid & 31;
    int lr = lane >> 2, lc = lane & 3;
    int bq = blockIdx.x, h = blockIdx.y, b = blockIdx.z;

    const __half* Kg = kv16 + ((size_t)b * NH + h) * SEQ * HD;
    const __half* Vg = kv16 + (((size_t)BATCH + b) * NH + h) * SEQ * HD;

    // Q loads (own cp.async group)
    #pragma unroll
    for (int i = 0; i < 4; ++i) {
        int ck = i * 256 + tid;
        int r = ck >> 3, seg = ck & 7;
        cp16(smem_u32(sQ + r * AQP + seg * 8),
             q16 + (((size_t)(bq * 128 + r) * BATCH + b) * DMODEL + h * HD + seg * 8));
    }
    asm volatile("cp.async.commit_group;" ::: "memory");

    auto load_kv = [&](int kb, int buf) {
        __half* Kb = sKV + buf * 2 * KVBUF;
        __half* Vb = Kb + KVBUF;
        #pragma unroll
        for (int i = 0; i < 2; ++i) {
            int ck = i * 256 + tid;
            int r = ck >> 3, seg = ck & 7;
            cp16(smem_u32(Kb + r * AQP + seg * 8),
                 Kg + (size_t)(kb * 64 + r) * HD + seg * 8);
            cp16(smem_u32(Vb + r * AQP + seg * 8),
                 Vg + (size_t)(kb * 64 + r) * HD + seg * 8);
        }
    };

    load_kv(0, 0);
    asm volatile("cp.async.commit_group;" ::: "memory");

    asm volatile("cp.async.wait_group 1;" ::: "memory");
    __syncthreads();
    uint32_t qa[4][4];
    #pragma unroll
    for (int kk = 0; kk < 4; ++kk)
        ldsm_x4(qa[kk], smem_u32(sQ + ((w * 16 + (lane & 15)) * AQP
                                       + kk * 16 + (lane >> 4) * 8)));

    float mrow[2] = {-1e30f, -1e30f};
    float lrow[2] = {0.f, 0.f};
    float O[8][4];
    #pragma unroll
    for (int ni = 0; ni < 8; ++ni)
        O[ni][0] = O[ni][1] = O[ni][2] = O[ni][3] = 0.f;

    for (int kb = 0; kb < NKB; ++kb) {
        if (kb + 1 < NKB) load_kv(kb + 1, (kb + 1) & 1);
        asm volatile("cp.async.commit_group;" ::: "memory");
        asm volatile("cp.async.wait_group 1;" ::: "memory");
        __syncthreads();

        uint32_t Kb = smem_u32(sKV + (kb & 1) * 2 * KVBUF);
        uint32_t Vb = Kb + KVBUF * 2;

        float S[8][4];
        #pragma unroll
        for (int ni = 0; ni < 8; ++ni)
            S[ni][0] = S[ni][1] = S[ni][2] = S[ni][3] = 0.f;
        #pragma unroll
        for (int kk = 0; kk < 4; ++kk) {
            #pragma unroll
            for (int ni = 0; ni < 8; ++ni) {
                uint32_t kf[2];
                ldsm_x2(kf, Kb + ((ni * 8 + (lane & 7)) * AQP
                                  + kk * 16 + ((lane >> 3) & 1) * 8) * 2);
                mma16816(S[ni], qa[kk], kf);
            }
        }

        #pragma unroll
        for (int hh = 0; hh < 2; ++hh) {
            float mx = -1e30f;
            #pragma unroll
            for (int ni = 0; ni < 8; ++ni)
                mx = fmaxf(mx, fmaxf(S[ni][2*hh], S[ni][2*hh+1]));
            mx = fmaxf(mx, __shfl_xor_sync(0xffffffffu, mx, 1));
            mx = fmaxf(mx, __shfl_xor_sync(0xffffffffu, mx, 2));
            float nm = fmaxf(mrow[hh], mx);
            float corr = __expf(mrow[hh] - nm);
            mrow[hh] = nm;
            float rs = 0.f;
            #pragma unroll
            for (int ni = 0; ni < 8; ++ni) {
                float p0 = __expf(S[ni][2*hh]   - nm);
                float p1 = __expf(S[ni][2*hh+1] - nm);
                S[ni][2*hh] = p0; S[ni][2*hh+1] = p1;
                rs += p0 + p1;
            }
            rs += __shfl_xor_sync(0xffffffffu, rs, 1);
            rs += __shfl_xor_sync(0xffffffffu, rs, 2);
            lrow[hh] = lrow[hh] * corr + rs;
            #pragma unroll
            for (int ni = 0; ni < 8; ++ni) {
                O[ni][2*hh]   *= corr;
                O[ni][2*hh+1] *= corr;
            }
        }

        #pragma unroll
        for (int kk = 0; kk < 4; ++kk) {
            uint32_t pa[4];
            pa[0] = pack_h2(S[2*kk][0],   S[2*kk][1]);
            pa[1] = pack_h2(S[2*kk][2],   S[2*kk][3]);
            pa[2] = pack_h2(S[2*kk+1][0], S[2*kk+1][1]);
            pa[3] = pack_h2(S[2*kk+1][2], S[2*kk+1][3]);
            #pragma unroll
            for (int ni = 0; ni < 8; ++ni) {
                uint32_t vf[2];
                ldsm_x2t(vf, Vb + ((kk * 16 + ((lane >> 3) & 1) * 8 + (lane & 7)) * AQP
                                   + ni * 8) * 2);
                mma16816(O[ni], pa, vf);
            }
        }
        __syncthreads();
    }

    #pragma unroll
    for (int hh = 0; hh < 2; ++hh) {
        int r = w * 16 + lr + hh * 8;
        int l = bq * 128 + r;
        float inv = 1.0f / lrow[hh];
        __half* po = out + (size_t)(l * BATCH + b) * DMODEL + h * HD;
        #pragma unroll
        for (int ni = 0; ni < 8; ++ni)
            *(__half2*)&po[ni * 8 + 2 * lc] =
                __floats2half2_rn(O[ni][2*hh] * inv, O[ni][2*hh+1] * inv);
    }
}

// ---------------- launcher --------------------------------------------------
extern "C" void kernel_launch(void* const* d_in, const int* in_sizes, int n_in,
                              void* d_out, int out_size)
{
    const float* x      = (const float*)d_in[0];
    const float* ln1_g  = (const float*)d_in[1];
    const float* ln1_b  = (const float*)d_in[2];
    const float* w_attn = (const float*)d_in[3];
    const float* b_attn = (const float*)d_in[4];
    const float* w_proj = (const float*)d_in[5];
    const float* b_proj = (const float*)d_in[6];
    const float* ln2_g  = (const float*)d_in[7];
    const float* ln2_b  = (const float*)d_in[8];
    const float* w_fc   = (const float*)d_in[9];
    const float* b_fc   = (const float*)d_in[10];
    const float* w_out  = (const float*)d_in[11];
    const float* b_out  = (const float*)d_in[12];

    float* out     = (float*)d_out;
    float* present = out + (size_t)SEQ * BATCH * DMODEL;

    __half *h16, *q16, *kv16, *attn16, *h2_16, *m16;
    __half *wt_attn, *wt_proj, *wt_fc, *wt_out;
    float *x1;
    cudaGetSymbolAddress((void**)&h16,     g_h16);
    cudaGetSymbolAddress((void**)&q16,     g_q16);
    cudaGetSymbolAddress((void**)&kv16,    g_kv16);
    cudaGetSymbolAddress((void**)&attn16,  g_attn16);
    cudaGetSymbolAddress((void**)&x1,      g_x1);
    cudaGetSymbolAddress((void**)&h2_16,   g_h2_16);
    cudaGetSymbolAddress((void**)&m16,     g_m16);
    cudaGetSymbolAddress((void**)&wt_attn, g_wt_attn);
    cudaGetSymbolAddress((void**)&wt_proj, g_wt_proj);
    cudaGetSymbolAddress((void**)&wt_fc,   g_wt_fc);
    cudaGetSymbolAddress((void**)&wt_out,  g_wt_out);

    cudaFuncSetAttribute(attn_kernel, cudaFuncAttributeMaxDynamicSharedMemorySize, ATTN_SMEM);
    cudaFuncSetAttribute(hgemm<0>, cudaFuncAttributeMaxDynamicSharedMemorySize, GEMM_SMEM);
    cudaFuncSetAttribute(hgemm<1>, cudaFuncAttributeMaxDynamicSharedMemorySize, GEMM_SMEM);
    cudaFuncSetAttribute(hgemm<2>, cudaFuncAttributeMaxDynamicSharedMemorySize, GEMM_SMEM);
    cudaFuncSetAttribute(hgemm<3>, cudaFuncAttributeMaxDynamicSharedMemorySize, GEMM_SMEM);

    dim3 tb(32, 8);
    // 0. weight transpose+convert to fp16 [N,K]
    transpose_w<<<dim3(3*DMODEL/32, DMODEL/32), tb>>>(w_attn, wt_attn, DMODEL, 3*DMODEL);
    transpose_w<<<dim3(DMODEL/32,   DMODEL/32), tb>>>(w_proj, wt_proj, DMODEL, DMODEL);
    transpose_w<<<dim3(DFF/32,      DMODEL/32), tb>>>(w_fc,   wt_fc,   DMODEL, DFF);
    transpose_w<<<dim3(DMODEL/32,   DFF/32),    tb>>>(w_out,  wt_out,  DFF,    DMODEL);

    // 1. h = LN1(x) -> fp16
    ln_kernel<<<ROWS, 256>>>(x, ln1_g, ln1_b, h16);
    // 2. qkv GEMM, fused split epilogue:
    //    Q -> q16 (fp16, x0.125), K/V -> present (fp32) + kv16 (fp16)
    hgemm<3><<<dim3(3*DMODEL/256, ROWS/128), 256, GEMM_SMEM>>>(
        h16, wt_attn, b_attn, nullptr, present, q16, kv16, ROWS, 3*DMODEL, DMODEL);
    // 3. attention -> attn16  [L,B,D] fp16
    attn_kernel<<<dim3(SEQ / 128, NH, BATCH), 256, ATTN_SMEM>>>(q16, kv16, attn16);
    // 4. x1 = x + attn @ w_proj + b_proj (fp32 out)
    hgemm<1><<<dim3(DMODEL/256, ROWS/128), 256, GEMM_SMEM>>>(
        attn16, wt_proj, b_proj, x, x1, nullptr, nullptr, ROWS, DMODEL, DMODEL);
    // 5. h2 = LN2(x1) -> fp16
    ln_kernel<<<ROWS, 256>>>(x1, ln2_g, ln2_b, h2_16);
    // 6. m = gelu(h2 @ w_fc + b_fc) -> fp16
    hgemm<2><<<dim3(DFF/256, ROWS/128), 256, GEMM_SMEM>>>(
        h2_16, wt_fc, b_fc, nullptr, nullptr, m16, nullptr, ROWS, DFF, DMODEL);
    // 7. out_x = x1 + m @ w_out + b_out (fp32 out)
    hgemm<1><<<dim3(DMODEL/256, ROWS/128), 256, GEMM_SMEM>>>(
        m16, wt_out, b_out, x1, out, nullptr, nullptr, ROWS, DMODEL, DFF);
}

// round 11
// speedup vs baseline: 6.3774x; 1.0162x over previous
#include <cuda_runtime.h>
#include <cuda_fp16.h>
#include <math.h>
#include <stdint.h>

#define SEQ    2048
#define BATCH  2
#define DMODEL 1024
#define NH     16
#define HD     64
#define DFF    4096
#define ROWS   (SEQ*BATCH)   // 4096

// ---------------- scratch (device globals; no allocation allowed) ----------
__device__ __half g_h16  [ROWS*DMODEL];      // LN1 out (fp16)
__device__ __half g_q16  [ROWS*DMODEL];      // Q (fp16, pre-scaled by 1/8)
__device__ __half g_kv16 [2*BATCH*NH*SEQ*HD];// K,V fp16 copy [2,B,H,L,hd]
__device__ __half g_attn16[ROWS*DMODEL];     // attention out (fp16)
__device__ float  g_x1   [ROWS*DMODEL];      // x + attn_proj (fp32)
__device__ __half g_h2_16[ROWS*DMODEL];      // LN2 out (fp16)
__device__ __half g_m16  [ROWS*DFF];         // gelu(fc) out (fp16)
// transposed fp16 weights [N,K]
__device__ __half g_wt_attn[3*DMODEL*DMODEL];
__device__ __half g_wt_proj[DMODEL*DMODEL];
__device__ __half g_wt_fc  [DFF*DMODEL];
__device__ __half g_wt_out [DMODEL*DFF];

// ---------------- helpers ----------------------------------------------------
__device__ __forceinline__ uint32_t smem_u32(const void* p)
{
    return (uint32_t)__cvta_generic_to_shared(p);
}

__device__ __forceinline__ void cp16(uint32_t dst, const void* src)
{
    asm volatile("cp.async.cg.shared.global [%0], [%1], 16;" :: "r"(dst), "l"(src) : "memory");
}

__device__ __forceinline__ void ldsm_x4(uint32_t* r, uint32_t addr)
{
    asm volatile("ldmatrix.sync.aligned.m8n8.x4.shared.b16 {%0,%1,%2,%3}, [%4];"
                 : "=r"(r[0]), "=r"(r[1]), "=r"(r[2]), "=r"(r[3]) : "r"(addr));
}

__device__ __forceinline__ void ldsm_x2(uint32_t* r, uint32_t addr)
{
    asm volatile("ldmatrix.sync.aligned.m8n8.x2.shared.b16 {%0,%1}, [%2];"
                 : "=r"(r[0]), "=r"(r[1]) : "r"(addr));
}

__device__ __forceinline__ void ldsm_x2t(uint32_t* r, uint32_t addr)
{
    asm volatile("ldmatrix.sync.aligned.m8n8.x2.trans.shared.b16 {%0,%1}, [%2];"
                 : "=r"(r[0]), "=r"(r[1]) : "r"(addr));
}

__device__ __forceinline__ void mma16816(float* c, const uint32_t* a, const uint32_t* b)
{
    asm volatile(
        "mma.sync.aligned.m16n8k16.row.col.f32.f16.f16.f32 "
        "{%0,%1,%2,%3}, {%4,%5,%6,%7}, {%8,%9}, {%0,%1,%2,%3};\n"
        : "+f"(c[0]), "+f"(c[1]), "+f"(c[2]), "+f"(c[3])
        : "r"(a[0]), "r"(a[1]), "r"(a[2]), "r"(a[3]),
          "r"(b[0]), "r"(b[1]));
}

__device__ __forceinline__ uint32_t pack_h2(float a, float b)
{
    __half2 h = __floats2half2_rn(a, b);
    return *reinterpret_cast<uint32_t*>(&h);
}

__device__ __forceinline__ float gelu_f(float v)
{
    float c = v + 0.044715f * v * v * v;
    return 0.5f * v * (1.0f + tanhf(0.7978845608028654f * c));
}

// ---------------- batched weight transpose+convert --------------------------
// one launch handles all 4 weights: W[K,N] f32 -> Wt[N,K] f16, 32x32 tiles
// tile ranges: attn [0,3072) ntx=96 | proj [3072,4096) ntx=32
//              fc   [4096,8192) ntx=128 | out [8192,12288) ntx=32
#define TT_TOTAL 12288
__global__ void transpose_all(const float* __restrict__ w0, const float* __restrict__ w1,
                              const float* __restrict__ w2, const float* __restrict__ w3,
                              __half* __restrict__ t0, __half* __restrict__ t1,
                              __half* __restrict__ t2, __half* __restrict__ t3)
{
    __shared__ float t[32][33];
    int tb = blockIdx.x;
    const float* W; __half* Wt; int K, N, ntx, local;
    if (tb < 3072)      { W = w0; Wt = t0; K = DMODEL; N = 3*DMODEL; ntx = 96;  local = tb; }
    else if (tb < 4096) { W = w1; Wt = t1; K = DMODEL; N = DMODEL;   ntx = 32;  local = tb - 3072; }
    else if (tb < 8192) { W = w2; Wt = t2; K = DMODEL; N = DFF;      ntx = 128; local = tb - 4096; }
    else                { W = w3; Wt = t3; K = DFF;    N = DMODEL;   ntx = 32;  local = tb - 8192; }
    int n0 = (local % ntx) * 32, k0 = (local / ntx) * 32;
    int tx = threadIdx.x, ty = threadIdx.y;
    #pragma unroll
    for (int d = 0; d < 32; d += 8)
        t[ty + d][tx] = W[(size_t)(k0 + ty + d) * N + n0 + tx];
    __syncthreads();
    #pragma unroll
    for (int d = 0; d < 32; d += 8)
        Wt[(size_t)(n0 + ty + d) * K + k0 + tx] = __float2half_rn(t[tx][ty + d]);
}

// ---------------- LayerNorm: one CTA per row, fp16 output ------------------
__global__ void ln_kernel(const float* __restrict__ x,
                          const float* __restrict__ g,
                          const float* __restrict__ b,
                          __half* __restrict__ y)
{
    int row = blockIdx.x;
    int tid = threadIdx.x;
    const float4* xr = reinterpret_cast<const float4*>(x + (size_t)row * DMODEL);
    float4 v = xr[tid];

    __shared__ float red[8];
    __shared__ float stat[2];

    float s = v.x + v.y + v.z + v.w;
    #pragma unroll
    for (int o = 16; o; o >>= 1) s += __shfl_xor_sync(0xffffffffu, s, o);
    if ((tid & 31) == 0) red[tid >> 5] = s;
    __syncthreads();
    if (tid == 0) {
        float t = 0.f;
        #pragma unroll
        for (int i = 0; i < 8; i++) t += red[i];
        stat[0] = t * (1.0f / DMODEL);
    }
    __syncthreads();
    float mu = stat[0];

    float dx = v.x - mu, dy = v.y - mu, dz = v.z - mu, dw = v.w - mu;
    float s2 = dx*dx + dy*dy + dz*dz + dw*dw;
    #pragma unroll
    for (int o = 16; o; o >>= 1) s2 += __shfl_xor_sync(0xffffffffu, s2, o);
    if ((tid & 31) == 0) red[tid >> 5] = s2;
    __syncthreads();
    if (tid == 0) {
        float t = 0.f;
        #pragma unroll
        for (int i = 0; i < 8; i++) t += red[i];
        stat[1] = rsqrtf(t * (1.0f / DMODEL) + 1e-5f);
    }
    __syncthreads();
    float rstd = stat[1];

    const float4* gr = reinterpret_cast<const float4*>(g);
    const float4* br = reinterpret_cast<const float4*>(b);
    float4 gv = gr[tid], bv = br[tid];
    __half2 p0 = __floats2half2_rn(dx * rstd * gv.x + bv.x, dy * rstd * gv.y + bv.y);
    __half2 p1 = __floats2half2_rn(dz * rstd * gv.z + bv.z, dw * rstd * gv.w + bv.w);
    __half2* yr = reinterpret_cast<__half2*>(y + (size_t)row * DMODEL);
    yr[tid * 2 + 0] = p0;
    yr[tid * 2 + 1] = p1;
}

// ---------------- fp16 mma.sync GEMM ----------------------------------------
// C[M,N] = A[M,K]f16 @ Bt[N,K]f16^T + epilogue, fp32 accum.
// 128x256 CTA tile, BK=32 halves, 4-stage cp.async ring, single sync/iter.
// 256 threads = 8 warps (2x4); warp tile 64x64 = 4m x 8n of m16n8k16.
// EPI: 0 = +bias (f32 out), 1 = +bias+res (f32 out), 2 = gelu(+bias) (f16 out)
// EPI 3 = qkv split: Q -> Ch (fp16, x0.125), K/V -> Cf (present fp32) + kvh (fp16)
#define BK        32
#define KROW      40                        // BK + 8 pad (halves); 80B stride
#define A_STAGE_B (128*KROW*2)              // 10240 bytes
#define B_STAGE_B (256*KROW*2)              // 20480 bytes
#define STAGE_B   (A_STAGE_B + B_STAGE_B)   // 30720 bytes
#define GSTAGES   4
#define GEMM_SMEM (GSTAGES*STAGE_B)         // 122880

template<int EPI>
__global__ void __launch_bounds__(256, 1)
hgemm(const __half* __restrict__ A, const __half* __restrict__ Bt,
      const float* __restrict__ bias, const float* __restrict__ res,
      float* __restrict__ Cf, __half* __restrict__ Ch,
      __half* __restrict__ kvh,
      int M, int N, int K)
{
    extern __shared__ char smem_raw[];
    uint32_t sbase = smem_u32(smem_raw);

    int tid = threadIdx.x;
    int w = tid >> 5, lane = tid & 31;
    int lr = lane >> 2, lc = lane & 3;
    int wm = w >> 2, wn = w & 3;                 // 2 x 4 warp grid
    int row0 = blockIdx.y * 128, col0 = blockIdx.x * 256;
    int KT = K / BK;

    float acc[4][8][4];
    #pragma unroll
    for (int i = 0; i < 4; ++i)
        #pragma unroll
        for (int j = 0; j < 8; ++j)
            acc[i][j][0] = acc[i][j][1] = acc[i][j][2] = acc[i][j][3] = 0.f;

    int ar = tid >> 2, seg = tid & 3;
    const char* Asrc0 = (const char*)(A + (size_t)(row0 + ar) * K + seg * 8);
    const char* Asrc1 = (const char*)(A + (size_t)(row0 + ar + 64) * K + seg * 8);
    const char* Bsrc0 = (const char*)(Bt + (size_t)(col0 + ar) * K + seg * 8);
    const char* Bsrc1 = (const char*)(Bt + (size_t)(col0 + ar + 64) * K + seg * 8);
    const char* Bsrc2 = (const char*)(Bt + (size_t)(col0 + ar + 128) * K + seg * 8);
    const char* Bsrc3 = (const char*)(Bt + (size_t)(col0 + ar + 192) * K + seg * 8);
    uint32_t dA0 = (uint32_t)(ar * KROW + seg * 8) * 2;
    uint32_t dA1 = dA0 + (uint32_t)(64 * KROW) * 2;
    uint32_t dB2 = dA0 + (uint32_t)(128 * KROW) * 2;
    uint32_t dB3 = dA0 + (uint32_t)(192 * KROW) * 2;

    int g = lane >> 3;   // 0..3
    uint32_t aFrag[2], bFrag[2];
    #pragma unroll
    for (int kk = 0; kk < 2; ++kk) {
        aFrag[kk] = (uint32_t)((wm * 64 + (lane & 15)) * KROW + kk * 16 + (lane >> 4) * 8) * 2;
        bFrag[kk] = (uint32_t)A_STAGE_B +
                    (uint32_t)((wn * 64 + (g >> 1) * 8 + (lane & 7)) * KROW
                               + kk * 16 + (g & 1) * 8) * 2;
    }

    auto load_stage = [&](int slot, int kc) {
        uint32_t ab = sbase + slot * STAGE_B;
        uint32_t bb = ab + A_STAGE_B;
        size_t koff = (size_t)kc * BK * 2;
        cp16(ab + dA0, Asrc0 + koff);
        cp16(ab + dA1, Asrc1 + koff);
        cp16(bb + dA0, Bsrc0 + koff);
        cp16(bb + dA1, Bsrc1 + koff);
        cp16(bb + dB2, Bsrc2 + koff);
        cp16(bb + dB3, Bsrc3 + koff);
    };

    #pragma unroll
    for (int c = 0; c < GSTAGES - 1; ++c) {
        load_stage(c, c);
        asm volatile("cp.async.commit_group;" ::: "memory");
    }

    for (int i = 0; i < KT; ++i) {
        asm volatile("cp.async.wait_group %0;" :: "n"(GSTAGES - 2) : "memory");
        __syncthreads();                           // single barrier per iter

        if (i + GSTAGES - 1 < KT)
            load_stage((i + GSTAGES - 1) & (GSTAGES - 1), i + GSTAGES - 1);
        asm volatile("cp.async.commit_group;" ::: "memory");

        uint32_t stg = sbase + (i & (GSTAGES - 1)) * STAGE_B;
        #pragma unroll
        for (int kk = 0; kk < 2; ++kk) {
            uint32_t af[4][4], bf[4][4];
            #pragma unroll
            for (int mi = 0; mi < 4; ++mi)
                ldsm_x4(af[mi], stg + aFrag[kk] + (uint32_t)(mi * 16 * KROW) * 2);
            #pragma unroll
            for (int np = 0; np < 4; ++np)
                ldsm_x4(bf[np], stg + bFrag[kk] + (uint32_t)(np * 16 * KROW) * 2);
            #pragma unroll
            for (int mi = 0; mi < 4; ++mi)
                #pragma unroll
                for (int np = 0; np < 4; ++np) {
                    mma16816(acc[mi][2*np],   af[mi], &bf[np][0]);
                    mma16816(acc[mi][2*np+1], af[mi], &bf[np][2]);
                }
        }
    }

    int sect = col0 >> 10;   // EPI==3: constant per tile (256 | 1024)

    #pragma unroll
    for (int mi = 0; mi < 4; ++mi) {
        #pragma unroll
        for (int hh = 0; hh < 2; ++hh) {
            int r = row0 + wm * 64 + mi * 16 + lr + hh * 8;
            #pragma unroll
            for (int ni = 0; ni < 8; ++ni) {
                int c = col0 + wn * 64 + ni * 8 + 2 * lc;
                float2 bv = *(const float2*)&bias[c];
                float ox = acc[mi][ni][2 * hh + 0] + bv.x;
                float oy = acc[mi][ni][2 * hh + 1] + bv.y;
                if (EPI == 1) {
                    float2 rv = *(const float2*)&res[(size_t)r * N + c];
                    ox += rv.x; oy += rv.y;
                }
                if (EPI == 2) {
                    *(__half2*)&Ch[(size_t)r * N + c] =
                        __floats2half2_rn(gelu_f(ox), gelu_f(oy));
                } else if (EPI == 3) {
                    if (sect == 0) {
                        *(__half2*)&Ch[(size_t)r * DMODEL + c] =
                            __floats2half2_rn(ox * 0.125f, oy * 0.125f);
                    } else {
                        int d  = c & (DMODEL - 1);
                        int hh2 = d >> 6, hd = d & (HD - 1);
                        int l = r >> 1, bb = r & 1;
                        size_t pidx = ((((size_t)(sect - 1) * BATCH + bb) * NH + hh2) * SEQ + l) * HD + hd;
                        *(float2*)&Cf[pidx] = make_float2(ox, oy);
                        *(__half2*)&kvh[pidx] = __floats2half2_rn(ox, oy);
                    }
                } else {
                    *(float2*)&Cf[(size_t)r * N + c] = make_float2(ox, oy);
                }
            }
        }
    }
}

// ---------------- Flash attention (fp16 mma.m16n8k16, register P) ----------
// CTA: 128 queries x (head, batch), 256 threads = 8 warps; warp w owns query
// rows 16w..16w+15. K/V fp16 via triple-buffered cp.async, one sync/iter.
#define AQP   72                         // row pitch (halves) = 144B
#define KVBUF (64*AQP)                   // halves per K (or V) tile
#define NBUF  3
#define ATTN_SMEM ((128*AQP + NBUF*2*KVBUF) * 2)
#define NKB   (SEQ/64)

__global__ void __launch_bounds__(256)
attn_kernel(const __half* __restrict__ q16, const __half* __restrict__ kv16,
            __half* __restrict__ out)
{
    extern __shared__ __half sh[];
    __half* sQ  = sh;                    // 128 x AQP
    __half* sKV = sh + 128 * AQP;        // NBUF x (K 64xAQP, V 64xAQP)

    int tid  = threadIdx.x;
    int w = tid >> 5, lane = tid & 31;
    int lr = lane >> 2, lc = lane & 3;
    int bq = blockIdx.x, h = blockIdx.y, b = blockIdx.z;

    const __half* Kg = kv16 + ((size_t)b * NH + h) * SEQ * HD;
    const __half* Vg = kv16 + (((size_t)BATCH + b) * NH + h) * SEQ * HD;

    // Q loads (own cp.async group)
    #pragma unroll
    for (int i = 0; i < 4; ++i) {
        int ck = i * 256 + tid;
        int r = ck >> 3, seg = ck & 7;
        cp16(smem_u32(sQ + r * AQP + seg * 8),
             q16 + (((size_t)(bq * 128 + r) * BATCH + b) * DMODEL + h * HD + seg * 8));
    }
    asm volatile("cp.async.commit_group;" ::: "memory");

    auto load_kv = [&](int kb, int buf) {
        __half* Kb = sKV + buf * 2 * KVBUF;
        __half* Vb = Kb + KVBUF;
        #pragma unroll
        for (int i = 0; i < 2; ++i) {
            int ck = i * 256 + tid;
            int r = ck >> 3, seg = ck & 7;
            cp16(smem_u32(Kb + r * AQP + seg * 8),
                 Kg + (size_t)(kb * 64 + r) * HD + seg * 8);
            cp16(smem_u32(Vb + r * AQP + seg * 8),
                 Vg + (size_t)(kb * 64 + r) * HD + seg * 8);
        }
    };

    load_kv(0, 0);
    asm volatile("cp.async.commit_group;" ::: "memory");
    load_kv(1, 1);
    asm volatile("cp.async.commit_group;" ::: "memory");

    // Q group done (2 KV groups may remain pending)
    asm volatile("cp.async.wait_group 2;" ::: "memory");
    __syncthreads();
    uint32_t qa[4][4];
    #pragma unroll
    for (int kk = 0; kk < 4; ++kk)
        ldsm_x4(qa[kk], smem_u32(sQ + ((w * 16 + (lane & 15)) * AQP
                                       + kk * 16 + (lane >> 4) * 8)));

    float mrow[2] = {-1e30f, -1e30f};
    float lrow[2] = {0.f, 0.f};
    float O[8][4];
    #pragma unroll
    for (int ni = 0; ni < 8; ++ni)
        O[ni][0] = O[ni][1] = O[ni][2] = O[ni][3] = 0.f;

    int buf = 0, nbuf = 2;   // buf of kb, buf to load next (kb+2)
    for (int kb = 0; kb < NKB; ++kb) {
        // buffer kb complete (only kb+1 may stay in flight)
        asm volatile("cp.async.wait_group 1;" ::: "memory");
        __syncthreads();     // all warps done with buffer nbuf's previous life

        if (kb + 2 < NKB) load_kv(kb + 2, nbuf);
        asm volatile("cp.async.commit_group;" ::: "memory");

        uint32_t Kb = smem_u32(sKV + buf * 2 * KVBUF);
        uint32_t Vb = Kb + KVBUF * 2;

        float S[8][4];
        #pragma unroll
        for (int ni = 0; ni < 8; ++ni)
            S[ni][0] = S[ni][1] = S[ni][2] = S[ni][3] = 0.f;
        #pragma unroll
        for (int kk = 0; kk < 4; ++kk) {
            #pragma unroll
            for (int ni = 0; ni < 8; ++ni) {
                uint32_t kf[2];
                ldsm_x2(kf, Kb + ((ni * 8 + (lane & 7)) * AQP
                                  + kk * 16 + ((lane >> 3) & 1) * 8) * 2);
                mma16816(S[ni], qa[kk], kf);
            }
        }

        #pragma unroll
        for (int hh = 0; hh < 2; ++hh) {
            float mx = -1e30f;
            #pragma unroll
            for (int ni = 0; ni < 8; ++ni)
                mx = fmaxf(mx, fmaxf(S[ni][2*hh], S[ni][2*hh+1]));
            mx = fmaxf(mx, __shfl_xor_sync(0xffffffffu, mx, 1));
            mx = fmaxf(mx, __shfl_xor_sync(0xffffffffu, mx, 2));
            float nm = fmaxf(mrow[hh], mx);
            float corr = __expf(mrow[hh] - nm);
            mrow[hh] = nm;
            float rs = 0.f;
            #pragma unroll
            for (int ni = 0; ni < 8; ++ni) {
                float p0 = __expf(S[ni][2*hh]   - nm);
                float p1 = __expf(S[ni][2*hh+1] - nm);
                S[ni][2*hh] = p0; S[ni][2*hh+1] = p1;
                rs += p0 + p1;
            }
            rs += __shfl_xor_sync(0xffffffffu, rs, 1);
            rs += __shfl_xor_sync(0xffffffffu, rs, 2);
            lrow[hh] = lrow[hh] * corr + rs;
            #pragma unroll
            for (int ni = 0; ni < 8; ++ni) {
                O[ni][2*hh]   *= corr;
                O[ni][2*hh+1] *= corr;
            }
        }

        #pragma unroll
        for (int kk = 0; kk < 4; ++kk) {
            uint32_t pa[4];
            pa[0] = pack_h2(S[2*kk][0],   S[2*kk][1]);
            pa[1] = pack_h2(S[2*kk][2],   S[2*kk][3]);
            pa[2] = pack_h2(S[2*kk+1][0], S[2*kk+1][1]);
            pa[3] = pack_h2(S[2*kk+1][2], S[2*kk+1][3]);
            #pragma unroll
            for (int ni = 0; ni < 8; ++ni) {
                uint32_t vf[2];
                ldsm_x2t(vf, Vb + ((kk * 16 + ((lane >> 3) & 1) * 8 + (lane & 7)) * AQP
                                   + ni * 8) * 2);
                mma16816(O[ni], pa, vf);
            }
        }

        buf  = (buf == NBUF - 1) ? 0 : buf + 1;
        nbuf = (nbuf == NBUF - 1) ? 0 : nbuf + 1;
    }

    #pragma unroll
    for (int hh = 0; hh < 2; ++hh) {
        int r = w * 16 + lr + hh * 8;
        int l = bq * 128 + r;
        float inv = 1.0f / lrow[hh];
        __half* po = out + (size_t)(l * BATCH + b) * DMODEL + h * HD;
        #pragma unroll
        for (int ni = 0; ni < 8; ++ni)
            *(__half2*)&po[ni * 8 + 2 * lc] =
                __floats2half2_rn(O[ni][2*hh] * inv, O[ni][2*hh+1] * inv);
    }
}

// ---------------- launcher --------------------------------------------------
extern "C" void kernel_launch(void* const* d_in, const int* in_sizes, int n_in,
                              void* d_out, int out_size)
{
    const float* x      = (const float*)d_in[0];
    const float* ln1_g  = (const float*)d_in[1];
    const float* ln1_b  = (const float*)d_in[2];
    const float* w_attn = (const float*)d_in[3];
    const float* b_attn = (const float*)d_in[4];
    const float* w_proj = (const float*)d_in[5];
    const float* b_proj = (const float*)d_in[6];
    const float* ln2_g  = (const float*)d_in[7];
    const float* ln2_b  = (const float*)d_in[8];
    const float* w_fc   = (const float*)d_in[9];
    const float* b_fc   = (const float*)d_in[10];
    const float* w_out  = (const float*)d_in[11];
    const float* b_out  = (const float*)d_in[12];

    float* out     = (float*)d_out;
    float* present = out + (size_t)SEQ * BATCH * DMODEL;

    __half *h16, *q16, *kv16, *attn16, *h2_16, *m16;
    __half *wt_attn, *wt_proj, *wt_fc, *wt_out;
    float *x1;
    cudaGetSymbolAddress((void**)&h16,     g_h16);
    cudaGetSymbolAddress((void**)&q16,     g_q16);
    cudaGetSymbolAddress((void**)&kv16,    g_kv16);
    cudaGetSymbolAddress((void**)&attn16,  g_attn16);
    cudaGetSymbolAddress((void**)&x1,      g_x1);
    cudaGetSymbolAddress((void**)&h2_16,   g_h2_16);
    cudaGetSymbolAddress((void**)&m16,     g_m16);
    cudaGetSymbolAddress((void**)&wt_attn, g_wt_attn);
    cudaGetSymbolAddress((void**)&wt_proj, g_wt_proj);
    cudaGetSymbolAddress((void**)&wt_fc,   g_wt_fc);
    cudaGetSymbolAddress((void**)&wt_out,  g_wt_out);

    cudaFuncSetAttribute(attn_kernel, cudaFuncAttributeMaxDynamicSharedMemorySize, ATTN_SMEM);
    cudaFuncSetAttribute(hgemm<0>, cudaFuncAttributeMaxDynamicSharedMemorySize, GEMM_SMEM);
    cudaFuncSetAttribute(hgemm<1>, cudaFuncAttributeMaxDynamicSharedMemorySize, GEMM_SMEM);
    cudaFuncSetAttribute(hgemm<2>, cudaFuncAttributeMaxDynamicSharedMemorySize, GEMM_SMEM);
    cudaFuncSetAttribute(hgemm<3>, cudaFuncAttributeMaxDynamicSharedMemorySize, GEMM_SMEM);

    // 0. weight transpose+convert to fp16 [N,K] (single batched launch)
    transpose_all<<<TT_TOTAL, dim3(32, 8)>>>(w_attn, w_proj, w_fc, w_out,
                                             wt_attn, wt_proj, wt_fc, wt_out);

    // 1. h = LN1(x) -> fp16
    ln_kernel<<<ROWS, 256>>>(x, ln1_g, ln1_b, h16);
    // 2. qkv GEMM, fused split epilogue:
    //    Q -> q16 (fp16, x0.125), K/V -> present (fp32) + kv16 (fp16)
    hgemm<3><<<dim3(3*DMODEL/256, ROWS/128), 256, GEMM_SMEM>>>(
        h16, wt_attn, b_attn, nullptr, present, q16, kv16, ROWS, 3*DMODEL, DMODEL);
    // 3. attention -> attn16  [L,B,D] fp16
    attn_kernel<<<dim3(SEQ / 128, NH, BATCH), 256, ATTN_SMEM>>>(q16, kv16, attn16);
    // 4. x1 = x + attn @ w_proj + b_proj (fp32 out)
    hgemm<1><<<dim3(DMODEL/256, ROWS/128), 256, GEMM_SMEM>>>(
        attn16, wt_proj, b_proj, x, x1, nullptr, nullptr, ROWS, DMODEL, DMODEL);
    // 5. h2 = LN2(x1) -> fp16
    ln_kernel<<<ROWS, 256>>>(x1, ln2_g, ln2_b, h2_16);
    // 6. m = gelu(h2 @ w_fc + b_fc) -> fp16
    hgemm<2><<<dim3(DFF/256, ROWS/128), 256, GEMM_SMEM>>>(
        h2_16, wt_fc, b_fc, nullptr, nullptr, m16, nullptr, ROWS, DFF, DMODEL);
    // 7. out_x = x1 + m @ w_out + b_out (fp32 out)
    hgemm<1><<<dim3(DMODEL/256, ROWS/128), 256, GEMM_SMEM>>>(
        m16, wt_out, b_out, x1, out, nullptr, nullptr, ROWS, DMODEL, DFF);
}

// round 12
// speedup vs baseline: 6.6279x; 1.0393x over previous
#include <cuda_runtime.h>
#include <cuda_fp16.h>
#include <math.h>
#include <stdint.h>

#define SEQ    2048
#define BATCH  2
#define DMODEL 1024
#define NH     16
#define HD     64
#define DFF    4096
#define ROWS   (SEQ*BATCH)   // 4096

// ---------------- scratch (device globals; no allocation allowed) ----------
__device__ __half g_h16  [ROWS*DMODEL];      // LN1 out (fp16)
__device__ __half g_q16  [ROWS*DMODEL];      // Q (fp16, pre-scaled by 1/8)
__device__ __half g_kv16 [2*BATCH*NH*SEQ*HD];// K,V fp16 copy [2,B,H,L,hd]
__device__ __half g_attn16[ROWS*DMODEL];     // attention out (fp16)
__device__ float  g_x1   [ROWS*DMODEL];      // x + attn_proj (fp32)
__device__ __half g_h2_16[ROWS*DMODEL];      // LN2 out (fp16)
__device__ __half g_m16  [ROWS*DFF];         // gelu(fc) out (fp16)
// transposed fp16 weights [N,K]
__device__ __half g_wt_attn[3*DMODEL*DMODEL];
__device__ __half g_wt_proj[DMODEL*DMODEL];
__device__ __half g_wt_fc  [DFF*DMODEL];
__device__ __half g_wt_out [DMODEL*DFF];

// ---------------- helpers ----------------------------------------------------
__device__ __forceinline__ uint32_t smem_u32(const void* p)
{
    return (uint32_t)__cvta_generic_to_shared(p);
}

__device__ __forceinline__ void cp16(uint32_t dst, const void* src)
{
    asm volatile("cp.async.cg.shared.global [%0], [%1], 16;" :: "r"(dst), "l"(src) : "memory");
}

__device__ __forceinline__ void ldsm_x4(uint32_t* r, uint32_t addr)
{
    asm volatile("ldmatrix.sync.aligned.m8n8.x4.shared.b16 {%0,%1,%2,%3}, [%4];"
                 : "=r"(r[0]), "=r"(r[1]), "=r"(r[2]), "=r"(r[3]) : "r"(addr));
}

__device__ __forceinline__ void ldsm_x2(uint32_t* r, uint32_t addr)
{
    asm volatile("ldmatrix.sync.aligned.m8n8.x2.shared.b16 {%0,%1}, [%2];"
                 : "=r"(r[0]), "=r"(r[1]) : "r"(addr));
}

__device__ __forceinline__ void ldsm_x2t(uint32_t* r, uint32_t addr)
{
    asm volatile("ldmatrix.sync.aligned.m8n8.x2.trans.shared.b16 {%0,%1}, [%2];"
                 : "=r"(r[0]), "=r"(r[1]) : "r"(addr));
}

__device__ __forceinline__ void mma16816(float* c, const uint32_t* a, const uint32_t* b)
{
    asm volatile(
        "mma.sync.aligned.m16n8k16.row.col.f32.f16.f16.f32 "
        "{%0,%1,%2,%3}, {%4,%5,%6,%7}, {%8,%9}, {%0,%1,%2,%3};\n"
        : "+f"(c[0]), "+f"(c[1]), "+f"(c[2]), "+f"(c[3])
        : "r"(a[0]), "r"(a[1]), "r"(a[2]), "r"(a[3]),
          "r"(b[0]), "r"(b[1]));
}

__device__ __forceinline__ uint32_t pack_h2(float a, float b)
{
    __half2 h = __floats2half2_rn(a, b);
    return *reinterpret_cast<uint32_t*>(&h);
}

__device__ __forceinline__ float gelu_f(float v)
{
    float c = v + 0.044715f * v * v * v;
    return 0.5f * v * (1.0f + tanhf(0.7978845608028654f * c));
}

// ---------------- batched weight transpose+convert --------------------------
#define TT_TOTAL 12288
__global__ void transpose_all(const float* __restrict__ w0, const float* __restrict__ w1,
                              const float* __restrict__ w2, const float* __restrict__ w3,
                              __half* __restrict__ t0, __half* __restrict__ t1,
                              __half* __restrict__ t2, __half* __restrict__ t3)
{
    __shared__ float t[32][33];
    int tb = blockIdx.x;
    const float* W; __half* Wt; int K, N, ntx, local;
    if (tb < 3072)      { W = w0; Wt = t0; K = DMODEL; N = 3*DMODEL; ntx = 96;  local = tb; }
    else if (tb < 4096) { W = w1; Wt = t1; K = DMODEL; N = DMODEL;   ntx = 32;  local = tb - 3072; }
    else if (tb < 8192) { W = w2; Wt = t2; K = DMODEL; N = DFF;      ntx = 128; local = tb - 4096; }
    else                { W = w3; Wt = t3; K = DFF;    N = DMODEL;   ntx = 32;  local = tb - 8192; }
    int n0 = (local % ntx) * 32, k0 = (local / ntx) * 32;
    int tx = threadIdx.x, ty = threadIdx.y;
    #pragma unroll
    for (int d = 0; d < 32; d += 8)
        t[ty + d][tx] = W[(size_t)(k0 + ty + d) * N + n0 + tx];
    __syncthreads();
    #pragma unroll
    for (int d = 0; d < 32; d += 8)
        Wt[(size_t)(n0 + ty + d) * K + k0 + tx] = __float2half_rn(t[tx][ty + d]);
}

// ---------------- LayerNorm: one CTA per row, fp16 output ------------------
__global__ void ln_kernel(const float* __restrict__ x,
                          const float* __restrict__ g,
                          const float* __restrict__ b,
                          __half* __restrict__ y)
{
    int row = blockIdx.x;
    int tid = threadIdx.x;
    const float4* xr = reinterpret_cast<const float4*>(x + (size_t)row * DMODEL);
    float4 v = xr[tid];

    __shared__ float red[8];
    __shared__ float stat[2];

    float s = v.x + v.y + v.z + v.w;
    #pragma unroll
    for (int o = 16; o; o >>= 1) s += __shfl_xor_sync(0xffffffffu, s, o);
    if ((tid & 31) == 0) red[tid >> 5] = s;
    __syncthreads();
    if (tid == 0) {
        float t = 0.f;
        #pragma unroll
        for (int i = 0; i < 8; i++) t += red[i];
        stat[0] = t * (1.0f / DMODEL);
    }
    __syncthreads();
    float mu = stat[0];

    float dx = v.x - mu, dy = v.y - mu, dz = v.z - mu, dw = v.w - mu;
    float s2 = dx*dx + dy*dy + dz*dz + dw*dw;
    #pragma unroll
    for (int o = 16; o; o >>= 1) s2 += __shfl_xor_sync(0xffffffffu, s2, o);
    if ((tid & 31) == 0) red[tid >> 5] = s2;
    __syncthreads();
    if (tid == 0) {
        float t = 0.f;
        #pragma unroll
        for (int i = 0; i < 8; i++) t += red[i];
        stat[1] = rsqrtf(t * (1.0f / DMODEL) + 1e-5f);
    }
    __syncthreads();
    float rstd = stat[1];

    const float4* gr = reinterpret_cast<const float4*>(g);
    const float4* br = reinterpret_cast<const float4*>(b);
    float4 gv = gr[tid], bv = br[tid];
    __half2 p0 = __floats2half2_rn(dx * rstd * gv.x + bv.x, dy * rstd * gv.y + bv.y);
    __half2 p1 = __floats2half2_rn(dz * rstd * gv.z + bv.z, dw * rstd * gv.w + bv.w);
    __half2* yr = reinterpret_cast<__half2*>(y + (size_t)row * DMODEL);
    yr[tid * 2 + 0] = p0;
    yr[tid * 2 + 1] = p1;
}

// ---------------- fp16 mma.sync GEMM ----------------------------------------
// C[M,N] = A[M,K]f16 @ Bt[N,K]f16^T + epilogue, fp32 accum.
// 128x256 CTA tile, BK=32 halves, 4-stage cp.async ring, single sync/iter.
// 512 threads = 16 warps (2x8); warp tile 64x32 = 4m x 4n of m16n8k16.
// ~118 regs/thread -> full 64K regfile at 1 CTA/SM, 4 warps/SMSP.
// EPI: 0 = +bias (f32 out), 1 = +bias+res (f32 out), 2 = gelu(+bias) (f16 out)
// EPI 3 = qkv split: Q -> Ch (fp16, x0.125), K/V -> Cf (present fp32) + kvh (fp16)
#define BK        32
#define KROW      40                        // BK + 8 pad (halves); 80B stride
#define A_STAGE_B (128*KROW*2)              // 10240 bytes
#define B_STAGE_B (256*KROW*2)              // 20480 bytes
#define STAGE_B   (A_STAGE_B + B_STAGE_B)   // 30720 bytes
#define GSTAGES   4
#define GEMM_SMEM (GSTAGES*STAGE_B)         // 122880

template<int EPI>
__global__ void __launch_bounds__(512, 1)
hgemm(const __half* __restrict__ A, const __half* __restrict__ Bt,
      const float* __restrict__ bias, const float* __restrict__ res,
      float* __restrict__ Cf, __half* __restrict__ Ch,
      __half* __restrict__ kvh,
      int M, int N, int K)
{
    extern __shared__ char smem_raw[];
    uint32_t sbase = smem_u32(smem_raw);

    int tid = threadIdx.x;
    int w = tid >> 5, lane = tid & 31;
    int lr = lane >> 2, lc = lane & 3;
    int wm = w >> 3, wn = w & 7;                 // 2 x 8 warp grid
    int row0 = blockIdx.y * 128, col0 = blockIdx.x * 256;
    int KT = K / BK;

    float acc[4][4][4];
    #pragma unroll
    for (int i = 0; i < 4; ++i)
        #pragma unroll
        for (int j = 0; j < 4; ++j)
            acc[i][j][0] = acc[i][j][1] = acc[i][j][2] = acc[i][j][3] = 0.f;

    // load mapping (16B chunks of 64B rows): chunk c -> row c>>2, seg c&2bits
    // A: 512 chunks = 1/thread.  B: 1024 chunks = 2/thread (rows br, br+128).
    int ar = tid >> 2, seg = tid & 3;
    const char* Asrc  = (const char*)(A + (size_t)(row0 + ar) * K + seg * 8);
    const char* Bsrc0 = (const char*)(Bt + (size_t)(col0 + ar) * K + seg * 8);
    const char* Bsrc1 = (const char*)(Bt + (size_t)(col0 + ar + 128) * K + seg * 8);
    uint32_t dA  = (uint32_t)(ar * KROW + seg * 8) * 2;
    uint32_t dB1 = dA + (uint32_t)(128 * KROW) * 2;

    // fragment smem offsets (within a stage)
    int g = lane >> 3;   // 0..3
    uint32_t aFrag[2], bFrag[2];
    #pragma unroll
    for (int kk = 0; kk < 2; ++kk) {
        aFrag[kk] = (uint32_t)((wm * 64 + (lane & 15)) * KROW + kk * 16 + (lane >> 4) * 8) * 2;
        bFrag[kk] = (uint32_t)A_STAGE_B +
                    (uint32_t)((wn * 32 + (g >> 1) * 8 + (lane & 7)) * KROW
                               + kk * 16 + (g & 1) * 8) * 2;
    }

    auto load_stage = [&](int slot, int kc) {
        uint32_t ab = sbase + slot * STAGE_B;
        uint32_t bb = ab + A_STAGE_B;
        size_t koff = (size_t)kc * BK * 2;
        cp16(ab + dA,  Asrc  + koff);
        cp16(bb + dA,  Bsrc0 + koff);
        cp16(bb + dB1, Bsrc1 + koff);
    };

    #pragma unroll
    for (int c = 0; c < GSTAGES - 1; ++c) {
        load_stage(c, c);
        asm volatile("cp.async.commit_group;" ::: "memory");
    }

    for (int i = 0; i < KT; ++i) {
        asm volatile("cp.async.wait_group %0;" :: "n"(GSTAGES - 2) : "memory");
        __syncthreads();                           // single barrier per iter

        if (i + GSTAGES - 1 < KT)
            load_stage((i + GSTAGES - 1) & (GSTAGES - 1), i + GSTAGES - 1);
        asm volatile("cp.async.commit_group;" ::: "memory");

        uint32_t stg = sbase + (i & (GSTAGES - 1)) * STAGE_B;
        #pragma unroll
        for (int kk = 0; kk < 2; ++kk) {
            uint32_t af[4][4], bf[2][4];
            #pragma unroll
            for (int mi = 0; mi < 4; ++mi)
                ldsm_x4(af[mi], stg + aFrag[kk] + (uint32_t)(mi * 16 * KROW) * 2);
            #pragma unroll
            for (int nb = 0; nb < 2; ++nb)
                ldsm_x4(bf[nb], stg + bFrag[kk] + (uint32_t)(nb * 16 * KROW) * 2);
            // bf[nb] = {n0k0, n0k8, n8k0, n8k8} -> B operands {bf[0],bf[1]} ... via g-trick:
            // actually layout from g-trick: bf = {nLo k0, nLo k8, nHi k0, nHi k8}
            #pragma unroll
            for (int mi = 0; mi < 4; ++mi)
                #pragma unroll
                for (int nb = 0; nb < 2; ++nb) {
                    mma16816(acc[mi][2*nb],   af[mi], &bf[nb][0]);
                    mma16816(acc[mi][2*nb+1], af[mi], &bf[nb][2]);
                }
        }
    }

    int sect = col0 >> 10;   // EPI==3: constant per tile (256 | 1024)

    #pragma unroll
    for (int mi = 0; mi < 4; ++mi) {
        #pragma unroll
        for (int hh = 0; hh < 2; ++hh) {
            int r = row0 + wm * 64 + mi * 16 + lr + hh * 8;
            #pragma unroll
            for (int ni = 0; ni < 4; ++ni) {
                int c = col0 + wn * 32 + ni * 8 + 2 * lc;
                float2 bv = *(const float2*)&bias[c];
                float ox = acc[mi][ni][2 * hh + 0] + bv.x;
                float oy = acc[mi][ni][2 * hh + 1] + bv.y;
                if (EPI == 1) {
                    float2 rv = *(const float2*)&res[(size_t)r * N + c];
                    ox += rv.x; oy += rv.y;
                }
                if (EPI == 2) {
                    *(__half2*)&Ch[(size_t)r * N + c] =
                        __floats2half2_rn(gelu_f(ox), gelu_f(oy));
                } else if (EPI == 3) {
                    if (sect == 0) {
                        *(__half2*)&Ch[(size_t)r * DMODEL + c] =
                            __floats2half2_rn(ox * 0.125f, oy * 0.125f);
                    } else {
                        int d  = c & (DMODEL - 1);
                        int hh2 = d >> 6, hd = d & (HD - 1);
                        int l = r >> 1, bb = r & 1;
                        size_t pidx = ((((size_t)(sect - 1) * BATCH + bb) * NH + hh2) * SEQ + l) * HD + hd;
                        *(float2*)&Cf[pidx] = make_float2(ox, oy);
                        *(__half2*)&kvh[pidx] = __floats2half2_rn(ox, oy);
                    }
                } else {
                    *(float2*)&Cf[(size_t)r * N + c] = make_float2(ox, oy);
                }
            }
        }
    }
}

// ---------------- Flash attention (fp16 mma.m16n8k16, register P) ----------
#define AQP   72                         // row pitch (halves) = 144B
#define KVBUF (64*AQP)                   // halves per K (or V) tile
#define NBUF  3
#define ATTN_SMEM ((128*AQP + NBUF*2*KVBUF) * 2)
#define NKB   (SEQ/64)

__global__ void __launch_bounds__(256)
attn_kernel(const __half* __restrict__ q16, const __half* __restrict__ kv16,
            __half* __restrict__ out)
{
    extern __shared__ __half sh[];
    __half* sQ  = sh;                    // 128 x AQP
    __half* sKV = sh + 128 * AQP;        // NBUF x (K 64xAQP, V 64xAQP)

    int tid  = threadIdx.x;
    int w = tid >> 5, lane = tid & 31;
    int lr = lane >> 2, lc = lane & 3;
    int bq = blockIdx.x, h = blockIdx.y, b = blockIdx.z;

    const __half* Kg = kv16 + ((size_t)b * NH + h) * SEQ * HD;
    const __half* Vg = kv16 + (((size_t)BATCH + b) * NH + h) * SEQ * HD;

    #pragma unroll
    for (int i = 0; i < 4; ++i) {
        int ck = i * 256 + tid;
        int r = ck >> 3, seg = ck & 7;
        cp16(smem_u32(sQ + r * AQP + seg * 8),
             q16 + (((size_t)(bq * 128 + r) * BATCH + b) * DMODEL + h * HD + seg * 8));
    }
    asm volatile("cp.async.commit_group;" ::: "memory");

    auto load_kv = [&](int kb, int buf) {
        __half* Kb = sKV + buf * 2 * KVBUF;
        __half* Vb = Kb + KVBUF;
        #pragma unroll
        for (int i = 0; i < 2; ++i) {
            int ck = i * 256 + tid;
            int r = ck >> 3, seg = ck & 7;
            cp16(smem_u32(Kb + r * AQP + seg * 8),
                 Kg + (size_t)(kb * 64 + r) * HD + seg * 8);
            cp16(smem_u32(Vb + r * AQP + seg * 8),
                 Vg + (size_t)(kb * 64 + r) * HD + seg * 8);
        }
    };

    load_kv(0, 0);
    asm volatile("cp.async.commit_group;" ::: "memory");
    load_kv(1, 1);
    asm volatile("cp.async.commit_group;" ::: "memory");

    asm volatile("cp.async.wait_group 2;" ::: "memory");
    __syncthreads();
    uint32_t qa[4][4];
    #pragma unroll
    for (int kk = 0; kk < 4; ++kk)
        ldsm_x4(qa[kk], smem_u32(sQ + ((w * 16 + (lane & 15)) * AQP
                                       + kk * 16 + (lane >> 4) * 8)));

    float mrow[2] = {-1e30f, -1e30f};
    float lrow[2] = {0.f, 0.f};
    float O[8][4];
    #pragma unroll
    for (int ni = 0; ni < 8; ++ni)
        O[ni][0] = O[ni][1] = O[ni][2] = O[ni][3] = 0.f;

    int buf = 0, nbuf = 2;
    for (int kb = 0; kb < NKB; ++kb) {
        asm volatile("cp.async.wait_group 1;" ::: "memory");
        __syncthreads();

        if (kb + 2 < NKB) load_kv(kb + 2, nbuf);
        asm volatile("cp.async.commit_group;" ::: "memory");

        uint32_t Kb = smem_u32(sKV + buf * 2 * KVBUF);
        uint32_t Vb = Kb + KVBUF * 2;

        float S[8][4];
        #pragma unroll
        for (int ni = 0; ni < 8; ++ni)
            S[ni][0] = S[ni][1] = S[ni][2] = S[ni][3] = 0.f;
        #pragma unroll
        for (int kk = 0; kk < 4; ++kk) {
            #pragma unroll
            for (int ni = 0; ni < 8; ++ni) {
                uint32_t kf[2];
                ldsm_x2(kf, Kb + ((ni * 8 + (lane & 7)) * AQP
                                  + kk * 16 + ((lane >> 3) & 1) * 8) * 2);
                mma16816(S[ni], qa[kk], kf);
            }
        }

        #pragma unroll
        for (int hh = 0; hh < 2; ++hh) {
            float mx = -1e30f;
            #pragma unroll
            for (int ni = 0; ni < 8; ++ni)
                mx = fmaxf(mx, fmaxf(S[ni][2*hh], S[ni][2*hh+1]));
            mx = fmaxf(mx, __shfl_xor_sync(0xffffffffu, mx, 1));
            mx = fmaxf(mx, __shfl_xor_sync(0xffffffffu, mx, 2));
            float nm = fmaxf(mrow[hh], mx);
            float corr = __expf(mrow[hh] - nm);
            mrow[hh] = nm;
            float rs = 0.f;
            #pragma unroll
            for (int ni = 0; ni < 8; ++ni) {
                float p0 = __expf(S[ni][2*hh]   - nm);
                float p1 = __expf(S[ni][2*hh+1] - nm);
                S[ni][2*hh] = p0; S[ni][2*hh+1] = p1;
                rs += p0 + p1;
            }
            rs += __shfl_xor_sync(0xffffffffu, rs, 1);
            rs += __shfl_xor_sync(0xffffffffu, rs, 2);
            lrow[hh] = lrow[hh] * corr + rs;
            #pragma unroll
            for (int ni = 0; ni < 8; ++ni) {
                O[ni][2*hh]   *= corr;
                O[ni][2*hh+1] *= corr;
            }
        }

        #pragma unroll
        for (int kk = 0; kk < 4; ++kk) {
            uint32_t pa[4];
            pa[0] = pack_h2(S[2*kk][0],   S[2*kk][1]);
            pa[1] = pack_h2(S[2*kk][2],   S[2*kk][3]);
            pa[2] = pack_h2(S[2*kk+1][0], S[2*kk+1][1]);
            pa[3] = pack_h2(S[2*kk+1][2], S[2*kk+1][3]);
            #pragma unroll
            for (int ni = 0; ni < 8; ++ni) {
                uint32_t vf[2];
                ldsm_x2t(vf, Vb + ((kk * 16 + ((lane >> 3) & 1) * 8 + (lane & 7)) * AQP
                                   + ni * 8) * 2);
                mma16816(O[ni], pa, vf);
            }
        }

        buf  = (buf == NBUF - 1) ? 0 : buf + 1;
        nbuf = (nbuf == NBUF - 1) ? 0 : nbuf + 1;
    }

    #pragma unroll
    for (int hh = 0; hh < 2; ++hh) {
        int r = w * 16 + lr + hh * 8;
        int l = bq * 128 + r;
        float inv = 1.0f / lrow[hh];
        __half* po = out + (size_t)(l * BATCH + b) * DMODEL + h * HD;
        #pragma unroll
        for (int ni = 0; ni < 8; ++ni)
            *(__half2*)&po[ni * 8 + 2 * lc] =
                __floats2half2_rn(O[ni][2*hh] * inv, O[ni][2*hh+1] * inv);
    }
}

// ---------------- launcher --------------------------------------------------
extern "C" void kernel_launch(void* const* d_in, const int* in_sizes, int n_in,
                              void* d_out, int out_size)
{
    const float* x      = (const float*)d_in[0];
    const float* ln1_g  = (const float*)d_in[1];
    const float* ln1_b  = (const float*)d_in[2];
    const float* w_attn = (const float*)d_in[3];
    const float* b_attn = (const float*)d_in[4];
    const float* w_proj = (const float*)d_in[5];
    const float* b_proj = (const float*)d_in[6];
    const float* ln2_g  = (const float*)d_in[7];
    const float* ln2_b  = (const float*)d_in[8];
    const float* w_fc   = (const float*)d_in[9];
    const float* b_fc   = (const float*)d_in[10];
    const float* w_out  = (const float*)d_in[11];
    const float* b_out  = (const float*)d_in[12];

    float* out     = (float*)d_out;
    float* present = out + (size_t)SEQ * BATCH * DMODEL;

    __half *h16, *q16, *kv16, *attn16, *h2_16, *m16;
    __half *wt_attn, *wt_proj, *wt_fc, *wt_out;
    float *x1;
    cudaGetSymbolAddress((void**)&h16,     g_h16);
    cudaGetSymbolAddress((void**)&q16,     g_q16);
    cudaGetSymbolAddress((void**)&kv16,    g_kv16);
    cudaGetSymbolAddress((void**)&attn16,  g_attn16);
    cudaGetSymbolAddress((void**)&x1,      g_x1);
    cudaGetSymbolAddress((void**)&h2_16,   g_h2_16);
    cudaGetSymbolAddress((void**)&m16,     g_m16);
    cudaGetSymbolAddress((void**)&wt_attn, g_wt_attn);
    cudaGetSymbolAddress((void**)&wt_proj, g_wt_proj);
    cudaGetSymbolAddress((void**)&wt_fc,   g_wt_fc);
    cudaGetSymbolAddress((void**)&wt_out,  g_wt_out);

    cudaFuncSetAttribute(attn_kernel, cudaFuncAttributeMaxDynamicSharedMemorySize, ATTN_SMEM);
    cudaFuncSetAttribute(hgemm<0>, cudaFuncAttributeMaxDynamicSharedMemorySize, GEMM_SMEM);
    cudaFuncSetAttribute(hgemm<1>, cudaFuncAttributeMaxDynamicSharedMemorySize, GEMM_SMEM);
    cudaFuncSetAttribute(hgemm<2>, cudaFuncAttributeMaxDynamicSharedMemorySize, GEMM_SMEM);
    cudaFuncSetAttribute(hgemm<3>, cudaFuncAttributeMaxDynamicSharedMemorySize, GEMM_SMEM);

    // 0. weight transpose+convert to fp16 [N,K] (single batched launch)
    transpose_all<<<TT_TOTAL, dim3(32, 8)>>>(w_attn, w_proj, w_fc, w_out,
                                             wt_attn, wt_proj, wt_fc, wt_out);

    // 1. h = LN1(x) -> fp16
    ln_kernel<<<ROWS, 256>>>(x, ln1_g, ln1_b, h16);
    // 2. qkv GEMM, fused split epilogue:
    //    Q -> q16 (fp16, x0.125), K/V -> present (fp32) + kv16 (fp16)
    hgemm<3><<<dim3(3*DMODEL/256, ROWS/128), 512, GEMM_SMEM>>>(
        h16, wt_attn, b_attn, nullptr, present, q16, kv16, ROWS, 3*DMODEL, DMODEL);
    // 3. attention -> attn16  [L,B,D] fp16
    attn_kernel<<<dim3(SEQ / 128, NH, BATCH), 256, ATTN_SMEM>>>(q16, kv16, attn16);
    // 4. x1 = x + attn @ w_proj + b_proj (fp32 out)
    hgemm<1><<<dim3(DMODEL/256, ROWS/128), 512, GEMM_SMEM>>>(
        attn16, wt_proj, b_proj, x, x1, nullptr, nullptr, ROWS, DMODEL, DMODEL);
    // 5. h2 = LN2(x1) -> fp16
    ln_kernel<<<ROWS, 256>>>(x1, ln2_g, ln2_b, h2_16);
    // 6. m = gelu(h2 @ w_fc + b_fc) -> fp16
    hgemm<2><<<dim3(DFF/256, ROWS/128), 512, GEMM_SMEM>>>(
        h2_16, wt_fc, b_fc, nullptr, nullptr, m16, nullptr, ROWS, DFF, DMODEL);
    // 7. out_x = x1 + m @ w_out + b_out (fp32 out)
    hgemm<1><<<dim3(DMODEL/256, ROWS/128), 512, GEMM_SMEM>>>(
        m16, wt_out, b_out, x1, out, nullptr, nullptr, ROWS, DMODEL, DFF);
}